// round 6
// baseline (speedup 1.0000x reference)
#include <cuda_runtime.h>
#include <math.h>

#define BB 256
#define NN 256
#define DD 256
#define UU 256

// ---------------------------------------------------------------------------
// Scratch (static __device__ arrays; no allocations allowed)
// ---------------------------------------------------------------------------
__device__ float g_fiou[(size_t)BB * NN * 1024];  // [b][n][1024]: 0..255=f_xb, 256..511=i, 512..767=o, 768..1023=u
__device__ float g_csh[(size_t)BB * NN * UU];     // child-sum of hidden
__device__ float g_gcs[(size_t)BB * NN * UU];     // gated child cell sum
__device__ float g_P0[BB * 768];                  // GEMM1 K-slice-0 partial [b][i|o|u]
__device__ float g_P1[BB * 768];                  // GEMM1 K-slice-1 partial
__device__ float g_out[BB * UU];                  // out for current step
__device__ float g_mem[BB * UU];                  // mem for current step

__device__ __forceinline__ float sigm(float x) { return 1.0f / (1.0f + expf(-x)); }

// ---------------------------------------------------------------------------
// Zero csh, gcs, hs (output is poisoned before every timed replay)
// ---------------------------------------------------------------------------
__global__ void k_zero(float4* __restrict__ hs4) {
    const size_t n4 = ((size_t)BB * NN * UU) / 4;
    float4 z = make_float4(0.f, 0.f, 0.f, 0.f);
    float4* c4 = (float4*)g_csh;
    float4* g4 = (float4*)g_gcs;
    for (size_t i = (size_t)blockIdx.x * blockDim.x + threadIdx.x; i < n4;
         i += (size_t)gridDim.x * blockDim.x) {
        c4[i] = z; g4[i] = z; hs4[i] = z;
    }
}

// ---------------------------------------------------------------------------
// Precompute: g_fiou = inputs @ x_fiou + bias
// C[65536 x 1024] = X[65536 x 256] @ W[256 x 1024]
// CTA tile 128x64, thread tile 8x4, K chunks of 16. FMA-issue bound.
// ---------------------------------------------------------------------------
__global__ void __launch_bounds__(256, 2) k_precompute(
    const float* __restrict__ X, const float* __restrict__ W,
    const float* __restrict__ bias)
{
    __shared__ float As[16 * 132];  // [k][row], padded
    __shared__ float Ws[16 * 64];   // [k][col]
    const int tid = threadIdx.x;
    const int ty  = tid >> 4;   // 0..15 -> rows ty*8..+7
    const int tx  = tid & 15;   // 0..15 -> cols tx*4..+3
    const int m0  = blockIdx.y * 128;
    const int n0  = blockIdx.x * 64;

    float acc[8][4];
#pragma unroll
    for (int i = 0; i < 8; ++i)
#pragma unroll
        for (int j = 0; j < 4; ++j) acc[i][j] = 0.f;

    for (int kc = 0; kc < DD; kc += 16) {
        // A chunk: 128 rows x 16 k, stored transposed As[k][row]
#pragma unroll
        for (int it = 0; it < 2; ++it) {
            int v = tid + it * 256;
            int r = v >> 2, q = v & 3;
            float4 a = *(const float4*)&X[(size_t)(m0 + r) * DD + kc + q * 4];
            As[(q * 4 + 0) * 132 + r] = a.x;
            As[(q * 4 + 1) * 132 + r] = a.y;
            As[(q * 4 + 2) * 132 + r] = a.z;
            As[(q * 4 + 3) * 132 + r] = a.w;
        }
        // W chunk: 16 k x 64 cols
        {
            int kk = tid >> 4, c4 = tid & 15;
            *(float4*)&Ws[kk * 64 + c4 * 4] =
                *(const float4*)&W[(size_t)(kc + kk) * 1024 + n0 + c4 * 4];
        }
        __syncthreads();
#pragma unroll
        for (int k = 0; k < 16; ++k) {
            float4 w  = *(const float4*)&Ws[k * 64 + tx * 4];
            float4 a0 = *(const float4*)&As[k * 132 + ty * 8];
            float4 a1 = *(const float4*)&As[k * 132 + ty * 8 + 4];
            float ar[8] = {a0.x, a0.y, a0.z, a0.w, a1.x, a1.y, a1.z, a1.w};
            float wr[4] = {w.x, w.y, w.z, w.w};
#pragma unroll
            for (int i = 0; i < 8; ++i)
#pragma unroll
                for (int j = 0; j < 4; ++j) acc[i][j] += ar[i] * wr[j];
        }
        __syncthreads();
    }
    float4 bv = *(const float4*)&bias[n0 + tx * 4];
#pragma unroll
    for (int i = 0; i < 8; ++i) {
        float4 o = make_float4(acc[i][0] + bv.x, acc[i][1] + bv.y,
                               acc[i][2] + bv.z, acc[i][3] + bv.w);
        *(float4*)&g_fiou[(size_t)(m0 + ty * 8 + i) * 1024 + n0 + tx * 4] = o;
    }
}

// ---------------------------------------------------------------------------
// Step kernel 1: IOU partial GEMM (K-split 2)
// P[ks][b][g*256 + u] = sum_{k in slice} csh[b, tgt[b]][k] * h_iou[k][g*256+u]
// Grid (8 b-tiles x 8 u-tiles x 2 k-slices) = 128 CTAs, 256 threads.
// ---------------------------------------------------------------------------
__global__ void __launch_bounds__(256) k_step1(
    const int* __restrict__ post, const float* __restrict__ hiou, int t)
{
    __shared__ float As[32 * 132];   // [row][k-local], 128 k per row
    __shared__ float Ws[64 * 96];    // [k-chunk][3 gates x 32 units]
    __shared__ int   stgt[32];

    const int tid = threadIdx.x;
    const int b0  = blockIdx.x * 32;
    const int u0  = blockIdx.y * 32;
    const int k0  = blockIdx.z * 128;

    if (tid < 32) {
        int po = post[(size_t)(b0 + tid) * NN + t];
        stgt[tid] = po < 0 ? 0 : po;
    }
    __syncthreads();

    // Gather csh rows (coalesced: warp per row, 512B segments)
    {
        int w = tid >> 5, q = tid & 31;
#pragma unroll
        for (int rr = 0; rr < 4; ++rr) {
            int r = w * 4 + rr;
            const float* src =
                &g_csh[(((size_t)(b0 + r)) * NN + stgt[r]) * UU + k0 + q * 4];
            *(float4*)&As[r * 132 + q * 4] = *(const float4*)src;
        }
    }

    const int tx = tid & 31;   // unit within tile
    const int ty = tid >> 5;   // 0..7 -> rows ty*4..+3
    float accI[4] = {0.f, 0.f, 0.f, 0.f};
    float accO[4] = {0.f, 0.f, 0.f, 0.f};
    float accU[4] = {0.f, 0.f, 0.f, 0.f};

    for (int kc = 0; kc < 128; kc += 64) {
        __syncthreads();  // first iter: As/stgt ready; later: Ws consumed
        // Load Ws chunk: 64 k-rows x (3 gates x 32 units)
#pragma unroll
        for (int j = 0; j < 6; ++j) {
            int idx = tid + j * 256;
            int kk  = idx / 24, rem = idx % 24;
            int g   = rem >> 3, q = rem & 7;
            *(float4*)&Ws[kk * 96 + g * 32 + q * 4] =
                *(const float4*)&hiou[(size_t)(k0 + kc + kk) * 768 + g * 256 + u0 + q * 4];
        }
        __syncthreads();
#pragma unroll 4
        for (int k = 0; k < 64; ++k) {
            float wi = Ws[k * 96 + tx];
            float wo = Ws[k * 96 + 32 + tx];
            float wu = Ws[k * 96 + 64 + tx];
#pragma unroll
            for (int i = 0; i < 4; ++i) {
                float a = As[(ty * 4 + i) * 132 + kc + k];
                accI[i] += a * wi;
                accO[i] += a * wo;
                accU[i] += a * wu;
            }
        }
    }

    float* P = blockIdx.z ? g_P1 : g_P0;
#pragma unroll
    for (int i = 0; i < 4; ++i) {
        int b = b0 + ty * 4 + i;
        P[b * 768 +       u0 + tx] = accI[i];
        P[b * 768 + 256 + u0 + tx] = accO[i];
        P[b * 768 + 512 + u0 + tx] = accU[i];
    }
}

// ---------------------------------------------------------------------------
// Step kernel 2a: gates. out = sig(o)*tanh(mem), mem = sig(i)*tanh(u)+gcs[tgt]
// Grid (8 b-tiles x 8 u-tiles) = 64 CTAs, 256 threads, 4 elems/thread.
// ---------------------------------------------------------------------------
__global__ void __launch_bounds__(256) k_step2a(const int* __restrict__ post, int t)
{
    __shared__ int stgt[32];
    const int tid = threadIdx.x;
    const int b0  = blockIdx.x * 32;
    const int u0  = blockIdx.y * 32;
    if (tid < 32) {
        int po = post[(size_t)(b0 + tid) * NN + t];
        stgt[tid] = po < 0 ? 0 : po;
    }
    __syncthreads();

    const int uu = tid & 31;
    const int rg = tid >> 5;
#pragma unroll
    for (int i = 0; i < 4; ++i) {
        int r  = rg * 4 + i;
        int b  = b0 + r;
        int tg = stgt[r];
        size_t fb = ((size_t)b * NN + tg) * 1024;
        int pj = b * 768 + u0 + uu;
        float iv = g_P0[pj]       + g_P1[pj]       + g_fiou[fb + 256 + u0 + uu];
        float ov = g_P0[pj + 256] + g_P1[pj + 256] + g_fiou[fb + 512 + u0 + uu];
        float uv = g_P0[pj + 512] + g_P1[pj + 512] + g_fiou[fb + 768 + u0 + uu];
        float gc = g_gcs[((size_t)b * NN + tg) * UU + u0 + uu];
        float mem  = sigm(iv) * tanhf(uv) + gc;
        float outv = sigm(ov) * tanhf(mem);
        g_out[b * UU + u0 + uu] = outv;
        g_mem[b * UU + u0 + uu] = mem;
    }
}

// ---------------------------------------------------------------------------
// Step kernel 2b: pre = out @ h_f; gated = sig(pre + f_xb[b,par]) * mem;
// scatter: hs[b,tgt] += out;  csh[b,par] += out;  gcs[b,par] += gated.
// Grid (8 b-tiles x 8 c-tiles) = 64 CTAs. Unique writer per element per step
// -> plain read-modify-write, no atomics.
// ---------------------------------------------------------------------------
__global__ void __launch_bounds__(256) k_step2b(
    const int* __restrict__ parents, const int* __restrict__ post,
    const float* __restrict__ hf, float* __restrict__ hs, int t)
{
    __shared__ float outS[32 * 260];  // [row][k], padded for 16B alignment
    __shared__ float hfS[64 * 32];    // [k-chunk][col]
    __shared__ float memS[32 * 36];   // [row][col-local]
    __shared__ int   stgt[32], spar[32], som[32], spm[32];

    const int tid = threadIdx.x;
    const int b0  = blockIdx.x * 32;
    const int c0  = blockIdx.y * 32;

    if (tid < 32) {
        int po = post[(size_t)(b0 + tid) * NN + t];
        int om = po >= 0;
        int tg = om ? po : 0;
        int pr = parents[(size_t)(b0 + tid) * NN + tg];
        stgt[tid] = tg;
        spar[tid] = pr < 0 ? 0 : pr;
        som[tid]  = om;
        spm[tid]  = om && (pr >= 0);
    }
    // Load out rows (all 256 k) and mem slice
#pragma unroll
    for (int j = 0; j < 8; ++j) {
        int idx = tid + j * 256;
        int r = idx >> 6, q = idx & 63;
        *(float4*)&outS[r * 260 + q * 4] =
            *(const float4*)&g_out[(b0 + r) * UU + q * 4];
    }
    {
        int r = tid >> 3, q = tid & 7;
        *(float4*)&memS[r * 36 + q * 4] =
            *(const float4*)&g_mem[(b0 + r) * UU + c0 + q * 4];
    }

    const int tx = tid & 15;   // cols c0 + tx*2, +1
    const int ty = tid >> 4;   // rows ty*2, +1
    float acc00 = 0.f, acc01 = 0.f, acc10 = 0.f, acc11 = 0.f;

    for (int kc = 0; kc < 256; kc += 64) {
        __syncthreads();  // first iter also covers outS/memS/index readiness
#pragma unroll
        for (int j = 0; j < 2; ++j) {
            int idx = tid + j * 256;
            int kk = idx >> 3, q = idx & 7;
            *(float4*)&hfS[kk * 32 + q * 4] =
                *(const float4*)&hf[(size_t)(kc + kk) * UU + c0 + q * 4];
        }
        __syncthreads();
#pragma unroll 4
        for (int k = 0; k < 64; ++k) {
            float a0 = outS[(ty * 2)     * 260 + kc + k];
            float a1 = outS[(ty * 2 + 1) * 260 + kc + k];
            float w0 = hfS[k * 32 + tx * 2];
            float w1 = hfS[k * 32 + tx * 2 + 1];
            acc00 += a0 * w0; acc01 += a0 * w1;
            acc10 += a1 * w0; acc11 += a1 * w1;
        }
    }

    float accs[2][2] = {{acc00, acc01}, {acc10, acc11}};
#pragma unroll
    for (int i = 0; i < 2; ++i)
#pragma unroll
        for (int j = 0; j < 2; ++j) {
            int r  = ty * 2 + i;
            int cl = tx * 2 + j;
            int b  = b0 + r;
            int c  = c0 + cl;
            float pre   = accs[i][j] + g_fiou[((size_t)b * NN + spar[r]) * 1024 + c];
            float gated = sigm(pre) * memS[r * 36 + cl];
            float outv  = outS[r * 260 + c];
            if (spm[r]) {
                size_t pi = ((size_t)b * NN + spar[r]) * UU + c;
                g_csh[pi] += outv;
                g_gcs[pi] += gated;
            }
            if (som[r]) {
                size_t hi = ((size_t)b * NN + stgt[r]) * UU + c;
                hs[hi] += outv;
            }
        }
}

// ---------------------------------------------------------------------------
// Launch: zero + precompute + 256 x (step1, step2a, step2b). 770 graph nodes.
// ---------------------------------------------------------------------------
extern "C" void kernel_launch(void* const* d_in, const int* in_sizes, int n_in,
                              void* d_out, int out_size)
{
    const float* inputs  = (const float*)d_in[0];
    const int*   parents = (const int*)  d_in[1];
    const int*   post    = (const int*)  d_in[2];
    const float* xf      = (const float*)d_in[3];
    const float* hfk     = (const float*)d_in[4];
    const float* hiou    = (const float*)d_in[5];
    const float* bias    = (const float*)d_in[6];
    float* hs = (float*)d_out;

    (void)in_sizes; (void)n_in; (void)out_size;

    k_zero<<<2048, 256>>>((float4*)hs);
    k_precompute<<<dim3(16, 512), 256>>>(inputs, xf, bias);

    for (int t = 0; t < NN; ++t) {
        k_step1 <<<dim3(8, 8, 2), 256>>>(post, hiou, t);
        k_step2a<<<dim3(8, 8),    256>>>(post, t);
        k_step2b<<<dim3(8, 8),    256>>>(parents, post, hfk, hs, t);
    }
}

// round 7
// speedup vs baseline: 1.0651x; 1.0651x over previous
#include <cuda_runtime.h>
#include <math.h>

#define BB 256
#define NN 256
#define DD 256
#define UU 256

// ---------------------------------------------------------------------------
// Scratch (static __device__ arrays; no allocations allowed)
// ---------------------------------------------------------------------------
__device__ float g_fiou[(size_t)BB * NN * 1024];  // [b][n][1024]: 0..255=f, 256..511=i, 512..767=o, 768..1023=u
__device__ float g_csh[(size_t)BB * NN * UU];     // child-sum of hidden
__device__ float g_gcs[(size_t)BB * NN * UU];     // gated child cell sum
__device__ float g_P0[BB * 768];                  // GEMM1 K-slice-0 partial [b][i|o|u]
__device__ float g_P1[BB * 768];                  // GEMM1 K-slice-1 partial
__device__ float g_out[BB * UU];                  // out for current step
__device__ float g_mem[BB * UU];                  // mem for current step

__device__ unsigned g_count = 0;
__device__ volatile unsigned g_gen = 0;

__device__ __forceinline__ float sigm(float x) { return 1.0f / (1.0f + expf(-x)); }

// Grid-wide sense-reversal barrier. All gridDim.x CTAs are co-resident
// (grid <= SM count, 1 CTA/SM), so spinning cannot deadlock.
__device__ __forceinline__ void gsync() {
    __syncthreads();
    if (threadIdx.x == 0) {
        unsigned my = g_gen;
        __threadfence();  // release: publish this CTA's global writes (to L2)
        if (atomicAdd(&g_count, 1u) == gridDim.x - 1) {
            g_count = 0;
            __threadfence();
            g_gen = my + 1;  // release everyone
        } else {
            while (g_gen == my) { }
        }
        __threadfence();  // acquire
    }
    __syncthreads();
}

// ---------------------------------------------------------------------------
// Zero csh, gcs, hs (output is poisoned before every timed replay)
// ---------------------------------------------------------------------------
__global__ void k_zero(float4* __restrict__ hs4) {
    const size_t n4 = ((size_t)BB * NN * UU) / 4;
    float4 z = make_float4(0.f, 0.f, 0.f, 0.f);
    float4* c4 = (float4*)g_csh;
    float4* g4 = (float4*)g_gcs;
    for (size_t i = (size_t)blockIdx.x * blockDim.x + threadIdx.x; i < n4;
         i += (size_t)gridDim.x * blockDim.x) {
        c4[i] = z; g4[i] = z; hs4[i] = z;
    }
}

// ---------------------------------------------------------------------------
// Precompute: g_fiou = inputs @ x_fiou + bias
// C[65536 x 1024] = X[65536 x 256] @ W[256 x 1024]
// CTA tile 128x64, thread tile 8x4, K chunks of 16. FMA-issue bound.
// ---------------------------------------------------------------------------
__global__ void __launch_bounds__(256, 2) k_precompute(
    const float* __restrict__ X, const float* __restrict__ W,
    const float* __restrict__ bias)
{
    __shared__ float As[16 * 132];  // [k][row], padded
    __shared__ float Ws[16 * 64];   // [k][col]
    const int tid = threadIdx.x;
    const int ty  = tid >> 4;
    const int tx  = tid & 15;
    const int m0  = blockIdx.y * 128;
    const int n0  = blockIdx.x * 64;

    float acc[8][4];
#pragma unroll
    for (int i = 0; i < 8; ++i)
#pragma unroll
        for (int j = 0; j < 4; ++j) acc[i][j] = 0.f;

    for (int kc = 0; kc < DD; kc += 16) {
#pragma unroll
        for (int it = 0; it < 2; ++it) {
            int v = tid + it * 256;
            int r = v >> 2, q = v & 3;
            float4 a = *(const float4*)&X[(size_t)(m0 + r) * DD + kc + q * 4];
            As[(q * 4 + 0) * 132 + r] = a.x;
            As[(q * 4 + 1) * 132 + r] = a.y;
            As[(q * 4 + 2) * 132 + r] = a.z;
            As[(q * 4 + 3) * 132 + r] = a.w;
        }
        {
            int kk = tid >> 4, c4 = tid & 15;
            *(float4*)&Ws[kk * 64 + c4 * 4] =
                *(const float4*)&W[(size_t)(kc + kk) * 1024 + n0 + c4 * 4];
        }
        __syncthreads();
#pragma unroll
        for (int k = 0; k < 16; ++k) {
            float4 w  = *(const float4*)&Ws[k * 64 + tx * 4];
            float4 a0 = *(const float4*)&As[k * 132 + ty * 8];
            float4 a1 = *(const float4*)&As[k * 132 + ty * 8 + 4];
            float ar[8] = {a0.x, a0.y, a0.z, a0.w, a1.x, a1.y, a1.z, a1.w};
            float wr[4] = {w.x, w.y, w.z, w.w};
#pragma unroll
            for (int i = 0; i < 8; ++i)
#pragma unroll
                for (int j = 0; j < 4; ++j) acc[i][j] += ar[i] * wr[j];
        }
        __syncthreads();
    }
    float4 bv = *(const float4*)&bias[n0 + tx * 4];
#pragma unroll
    for (int i = 0; i < 8; ++i) {
        float4 o = make_float4(acc[i][0] + bv.x, acc[i][1] + bv.y,
                               acc[i][2] + bv.z, acc[i][3] + bv.w);
        *(float4*)&g_fiou[(size_t)(m0 + ty * 8 + i) * 1024 + n0 + tx * 4] = o;
    }
}

// ---------------------------------------------------------------------------
// Persistent recurrence: 128 CTAs x 256 threads, 256 steps, 3 phases/step.
//
// Cross-CTA mutable data (csh, gcs, P0/P1, out, mem) is READ via __ldcg
// (L2-only; L1 is not coherent across SMs) and published by the barrier's
// __threadfence. Read-only weights use normal loads so L1 keeps them hot
// across all 256 steps. Per step there is one node per batch element, so
// every scatter destination (b, parent, col) has a unique writer.
// ---------------------------------------------------------------------------
__global__ void __launch_bounds__(256, 1) k_recur(
    const int*   __restrict__ parents,
    const int*   __restrict__ post,
    const float* __restrict__ hf,
    const float* __restrict__ hiou,
    float*       __restrict__ hs)
{
    __shared__ __align__(16) float sm[11520];  // 46.08 KB, unioned across phases
    const int c   = blockIdx.x;
    const int tid = threadIdx.x;

    for (int t = 0; t < NN; ++t) {
        // =========== Phase 1: IOU partial GEMM (csh[.,tgt] @ h_iou) ===========
        {
            const int b0 = (c & 7) * 32;
            const int u0 = ((c >> 3) & 7) * 32;
            const int k0 = (c >> 6) * 128;          // K-split slice
            float* As = sm;                          // [32][132]
            float* Ws = sm + 4224;                   // [64][96]

            // Gather csh rows (32 rows x 128 k of this slice), coalesced
            {
                int r = tid >> 3, q = tid & 7;
                int po = post[(b0 + r) * NN + t];
                int tg = po < 0 ? 0 : po;
                const float4* src =
                    (const float4*)&g_csh[(((size_t)(b0 + r)) * NN + tg) * UU + k0];
#pragma unroll
                for (int j = 0; j < 4; ++j) {
                    float4 v = __ldcg(&src[q + j * 8]);
                    *(float4*)&As[r * 132 + (q + j * 8) * 4] = v;
                }
            }

            const int tx = tid & 15;   // unit pair within 32-wide gate block
            const int ty = tid >> 4;   // rows ty*2, ty*2+1
            float acc[2][6];
#pragma unroll
            for (int i = 0; i < 2; ++i)
#pragma unroll
                for (int j = 0; j < 6; ++j) acc[i][j] = 0.f;

            for (int kc = 0; kc < 128; kc += 64) {
                __syncthreads();
                // Ws chunk: 64 k-rows x (3 gates x 32 units)
#pragma unroll
                for (int j = 0; j < 6; ++j) {
                    int idx = tid + j * 256;
                    int kk = idx / 24, rem = idx % 24;
                    int g = rem >> 3, qq = rem & 7;
                    *(float4*)&Ws[kk * 96 + g * 32 + qq * 4] =
                        *(const float4*)&hiou[(size_t)(k0 + kc + kk) * 768 +
                                              g * 256 + u0 + qq * 4];
                }
                __syncthreads();
#pragma unroll 4
                for (int k = 0; k < 64; ++k) {
                    float a0 = As[(ty * 2)     * 132 + kc + k];
                    float a1 = As[(ty * 2 + 1) * 132 + kc + k];
                    float2 wi = *(float2*)&Ws[k * 96 +       tx * 2];
                    float2 wo = *(float2*)&Ws[k * 96 + 32 + tx * 2];
                    float2 wu = *(float2*)&Ws[k * 96 + 64 + tx * 2];
                    acc[0][0] += a0 * wi.x; acc[0][1] += a0 * wi.y;
                    acc[0][2] += a0 * wo.x; acc[0][3] += a0 * wo.y;
                    acc[0][4] += a0 * wu.x; acc[0][5] += a0 * wu.y;
                    acc[1][0] += a1 * wi.x; acc[1][1] += a1 * wi.y;
                    acc[1][2] += a1 * wo.x; acc[1][3] += a1 * wo.y;
                    acc[1][4] += a1 * wu.x; acc[1][5] += a1 * wu.y;
                }
            }
            float* P = (c >> 6) ? g_P1 : g_P0;
#pragma unroll
            for (int i = 0; i < 2; ++i) {
                int b = (c & 7) * 32 + ty * 2 + i;
                *(float2*)&P[b * 768 +       u0 + tx * 2] = make_float2(acc[i][0], acc[i][1]);
                *(float2*)&P[b * 768 + 256 + u0 + tx * 2] = make_float2(acc[i][2], acc[i][3]);
                *(float2*)&P[b * 768 + 512 + u0 + tx * 2] = make_float2(acc[i][4], acc[i][5]);
            }
        }
        gsync();

        // =========== Phase 2: gates (2 rows per CTA) ===========
        {
            int b  = c * 2 + (tid >> 7);
            int u  = (tid & 127) * 2;
            int po = post[b * NN + t];
            int tg = po < 0 ? 0 : po;
            size_t fb = ((size_t)b * NN + tg) * 1024;

            float2 i0 = __ldcg((const float2*)&g_P0[b * 768 + u]);
            float2 i1 = __ldcg((const float2*)&g_P1[b * 768 + u]);
            float2 o0 = __ldcg((const float2*)&g_P0[b * 768 + 256 + u]);
            float2 o1 = __ldcg((const float2*)&g_P1[b * 768 + 256 + u]);
            float2 u0v = __ldcg((const float2*)&g_P0[b * 768 + 512 + u]);
            float2 u1v = __ldcg((const float2*)&g_P1[b * 768 + 512 + u]);
            float2 fi = *(const float2*)&g_fiou[fb + 256 + u];
            float2 fo = *(const float2*)&g_fiou[fb + 512 + u];
            float2 fu = *(const float2*)&g_fiou[fb + 768 + u];
            float2 gc = __ldcg((const float2*)&g_gcs[((size_t)b * NN + tg) * UU + u]);

            float memx = sigm(i0.x + i1.x + fi.x) * tanhf(u0v.x + u1v.x + fu.x) + gc.x;
            float memy = sigm(i0.y + i1.y + fi.y) * tanhf(u0v.y + u1v.y + fu.y) + gc.y;
            float outx = sigm(o0.x + o1.x + fo.x) * tanhf(memx);
            float outy = sigm(o0.y + o1.y + fo.y) * tanhf(memy);
            *(float2*)&g_out[b * UU + u] = make_float2(outx, outy);
            *(float2*)&g_mem[b * UU + u] = make_float2(memx, memy);
        }
        gsync();

        // =========== Phase 3: GEMM2 (out @ h_f) + gated + scatter ===========
        if (c < 64) {
            const int b0 = (c >> 3) * 32;
            const int c0 = (c & 7) * 32;
            float* outS = sm;                 // [32][260]
            float* hfS  = sm + 8320;          // [64][32]
            float* memS = sm + 8320 + 2048;   // [32][36]

#pragma unroll
            for (int j = 0; j < 8; ++j) {
                int idx = tid + j * 256;
                int r = idx >> 6, q = idx & 63;
                float4 v = __ldcg((const float4*)&g_out[(b0 + r) * UU + q * 4]);
                *(float4*)&outS[r * 260 + q * 4] = v;
            }
            {
                int r = tid >> 3, q = tid & 7;
                float4 v = __ldcg((const float4*)&g_mem[(b0 + r) * UU + c0 + q * 4]);
                *(float4*)&memS[r * 36 + q * 4] = v;
            }

            const int tx = tid & 15;
            const int ty = tid >> 4;
            float acc00 = 0.f, acc01 = 0.f, acc10 = 0.f, acc11 = 0.f;

            for (int kc = 0; kc < 256; kc += 64) {
                __syncthreads();
#pragma unroll
                for (int j = 0; j < 2; ++j) {
                    int idx = tid + j * 256;
                    int kk = idx >> 3, q = idx & 7;
                    *(float4*)&hfS[kk * 32 + q * 4] =
                        *(const float4*)&hf[(size_t)(kc + kk) * UU + c0 + q * 4];
                }
                __syncthreads();
#pragma unroll 4
                for (int k = 0; k < 64; ++k) {
                    float a0 = outS[(ty * 2)     * 260 + kc + k];
                    float a1 = outS[(ty * 2 + 1) * 260 + kc + k];
                    float2 w = *(float2*)&hfS[k * 32 + tx * 2];
                    acc00 += a0 * w.x; acc01 += a0 * w.y;
                    acc10 += a1 * w.x; acc11 += a1 * w.y;
                }
            }

            float accs[2][2] = {{acc00, acc01}, {acc10, acc11}};
#pragma unroll
            for (int i = 0; i < 2; ++i) {
                int r  = ty * 2 + i;
                int b  = b0 + r;
                int po = post[b * NN + t];
                int om = po >= 0;
                int tg = om ? po : 0;
                int pr = parents[b * NN + tg];
                int pm = om && (pr >= 0);
                int pa = pr < 0 ? 0 : pr;
#pragma unroll
                for (int j = 0; j < 2; ++j) {
                    int cl = tx * 2 + j;
                    int cc = c0 + cl;
                    float pre   = accs[i][j] +
                                  g_fiou[((size_t)b * NN + pa) * 1024 + cc];
                    float gated = sigm(pre) * memS[r * 36 + cl];
                    float outv  = outS[r * 260 + cc];
                    if (pm) {  // this CTA owns all (b, *, cc): local RMW is safe
                        size_t pi = ((size_t)b * NN + pa) * UU + cc;
                        g_csh[pi] += outv;
                        g_gcs[pi] += gated;
                    }
                    if (om) {
                        size_t hi = ((size_t)b * NN + tg) * UU + cc;
                        hs[hi] += outv;
                    }
                }
            }
        }
        gsync();
    }
}

// ---------------------------------------------------------------------------
// Launch: 3 graph nodes total.
// ---------------------------------------------------------------------------
extern "C" void kernel_launch(void* const* d_in, const int* in_sizes, int n_in,
                              void* d_out, int out_size)
{
    const float* inputs  = (const float*)d_in[0];
    const int*   parents = (const int*)  d_in[1];
    const int*   post    = (const int*)  d_in[2];
    const float* xf      = (const float*)d_in[3];
    const float* hfk     = (const float*)d_in[4];
    const float* hiou    = (const float*)d_in[5];
    const float* bias    = (const float*)d_in[6];
    float* hs = (float*)d_out;

    (void)in_sizes; (void)n_in; (void)out_size;

    k_zero<<<2048, 256>>>((float4*)hs);
    k_precompute<<<dim3(16, 512), 256>>>(inputs, xf, bias);
    k_recur<<<128, 256>>>(parents, post, hfk, hiou, hs);
}

// round 8
// speedup vs baseline: 1.5196x; 1.4267x over previous
#include <cuda_runtime.h>
#include <math.h>

#define BB 256
#define NN 256
#define DD 256
#define UU 256

// ---------------------------------------------------------------------------
// Scratch (static __device__ arrays; no allocations allowed)
// ---------------------------------------------------------------------------
__device__ float g_fiou[(size_t)BB * NN * 1024];  // [b][n][1024]: 0..255=f, 256..511=i, 512..767=o, 768..1023=u
__device__ float g_csh[(size_t)BB * NN * UU];     // child-sum of hidden
__device__ float g_gcs[(size_t)BB * NN * UU];     // gated child cell sum
__device__ float g_out[BB * UU];                  // out for current step
__device__ float g_mem[BB * UU];                  // mem for current step

__device__ unsigned g_count = 0;
__device__ volatile unsigned g_gen = 0;

// Fast transcendentals: __expf rel-err ~2^-21, far inside the 1e-3 budget.
__device__ __forceinline__ float sigm_(float x) {
    return __fdividef(1.f, 1.f + __expf(-x));
}
__device__ __forceinline__ float tanh_(float x) {
    x = fminf(fmaxf(x, -15.f), 15.f);   // avoid inf/inf; tanh saturates anyway
    float e = __expf(2.f * x);
    return __fdividef(e - 1.f, e + 1.f);
}

// Grid-wide sense-reversal barrier; 128 CTAs co-resident (1/SM) so spin is safe.
__device__ __forceinline__ void gsync() {
    __syncthreads();
    if (threadIdx.x == 0) {
        unsigned my = g_gen;
        __threadfence();  // release: publish this CTA's global writes to L2
        if (atomicAdd(&g_count, 1u) == gridDim.x - 1) {
            g_count = 0;
            __threadfence();
            g_gen = my + 1;
        } else {
            while (g_gen == my) { }
        }
        __threadfence();  // acquire
    }
    __syncthreads();
}

// ---------------------------------------------------------------------------
// Zero csh, gcs (output hs is written by pure stores; no zeroing needed there,
// but it is poisoned each run and masked rows must still be 0 -> zero it too)
// ---------------------------------------------------------------------------
__global__ void k_zero(float4* __restrict__ hs4) {
    const size_t n4 = ((size_t)BB * NN * UU) / 4;
    float4 z = make_float4(0.f, 0.f, 0.f, 0.f);
    float4* c4 = (float4*)g_csh;
    float4* g4 = (float4*)g_gcs;
    for (size_t i = (size_t)blockIdx.x * blockDim.x + threadIdx.x; i < n4;
         i += (size_t)gridDim.x * blockDim.x) {
        c4[i] = z; g4[i] = z; hs4[i] = z;
    }
}

// ---------------------------------------------------------------------------
// Precompute: g_fiou = inputs @ x_fiou + bias   (unchanged from R6)
// ---------------------------------------------------------------------------
__global__ void __launch_bounds__(256, 2) k_precompute(
    const float* __restrict__ X, const float* __restrict__ W,
    const float* __restrict__ bias)
{
    __shared__ float As[16 * 132];
    __shared__ float Ws[16 * 64];
    const int tid = threadIdx.x;
    const int ty  = tid >> 4;
    const int tx  = tid & 15;
    const int m0  = blockIdx.y * 128;
    const int n0  = blockIdx.x * 64;

    float acc[8][4];
#pragma unroll
    for (int i = 0; i < 8; ++i)
#pragma unroll
        for (int j = 0; j < 4; ++j) acc[i][j] = 0.f;

    for (int kc = 0; kc < DD; kc += 16) {
#pragma unroll
        for (int it = 0; it < 2; ++it) {
            int v = tid + it * 256;
            int r = v >> 2, q = v & 3;
            float4 a = *(const float4*)&X[(size_t)(m0 + r) * DD + kc + q * 4];
            As[(q * 4 + 0) * 132 + r] = a.x;
            As[(q * 4 + 1) * 132 + r] = a.y;
            As[(q * 4 + 2) * 132 + r] = a.z;
            As[(q * 4 + 3) * 132 + r] = a.w;
        }
        {
            int kk = tid >> 4, c4 = tid & 15;
            *(float4*)&Ws[kk * 64 + c4 * 4] =
                *(const float4*)&W[(size_t)(kc + kk) * 1024 + n0 + c4 * 4];
        }
        __syncthreads();
#pragma unroll
        for (int k = 0; k < 16; ++k) {
            float4 w  = *(const float4*)&Ws[k * 64 + tx * 4];
            float4 a0 = *(const float4*)&As[k * 132 + ty * 8];
            float4 a1 = *(const float4*)&As[k * 132 + ty * 8 + 4];
            float ar[8] = {a0.x, a0.y, a0.z, a0.w, a1.x, a1.y, a1.z, a1.w};
            float wr[4] = {w.x, w.y, w.z, w.w};
#pragma unroll
            for (int i = 0; i < 8; ++i)
#pragma unroll
                for (int j = 0; j < 4; ++j) acc[i][j] += ar[i] * wr[j];
        }
        __syncthreads();
    }
    float4 bv = *(const float4*)&bias[n0 + tx * 4];
#pragma unroll
    for (int i = 0; i < 8; ++i) {
        float4 o = make_float4(acc[i][0] + bv.x, acc[i][1] + bv.y,
                               acc[i][2] + bv.z, acc[i][3] + bv.w);
        *(float4*)&g_fiou[(size_t)(m0 + ty * 8 + i) * 1024 + n0 + tx * 4] = o;
    }
}

// ---------------------------------------------------------------------------
// Persistent recurrence: 128 CTAs x 256 threads, 256 steps, 2 phases/step.
//
// Phase A (all CTAs): full-K GEMM1 tile (32 rows x 16 units x 3 gates) +
//   gates fused locally -> writes g_out/g_mem. Cross-CTA reads via __ldcg.
// Phase C (all CTAs): GEMM2 (out @ h_f, 16 rows x 32 cols) + gated scatter.
//   csh/gcs ownership is (b-tile, col-tile) -> fixed CTA per element across
//   steps, so its RMW uses normal loads (same-SM L1 is coherent with itself;
//   STG is write-through so phase A's __ldcg sees L2).
// hs is written with a pure store: each (b, node) is visited exactly once.
// ---------------------------------------------------------------------------
__global__ void __launch_bounds__(256, 1) k_recur(
    const int*   __restrict__ parents,
    const int*   __restrict__ post,
    const float* __restrict__ hf,
    const float* __restrict__ hiou,
    float*       __restrict__ hs)
{
    __shared__ __align__(16) float sm[11392];  // A: As 32x260 + Ws 64x48 = 45.6KB
    const int c   = blockIdx.x;
    const int tid = threadIdx.x;

    // Phase A tiling: 8 b-tiles(32) x 16 u-tiles(16)
    const int bA0 = (c & 7) * 32;
    const int uA0 = (c >> 3) * 16;
    // Phase C tiling: 16 b-tiles(16) x 8 col-tiles(32)
    const int bC0 = (c & 15) * 16;
    const int cC0 = (c >> 4) * 32;

    const int tx = tid & 15;
    const int ty = tid >> 4;

    float* As = sm;            // [32][260]
    float* Ws = sm + 8320;     // [64][48]
    float* outS = sm;          // [16][260] (phase C)
    float* hfS  = sm + 4160;   // [64][36]  (phase C)

    for (int t = 0; t < NN; ++t) {
        // ================= Phase A: GEMM1 + gates =================
        {
            const int rowA0 = bA0 + ty * 2;
            const int rowA1 = rowA0 + 1;
            const int u     = uA0 + tx;

            // Index + operand prefetch (latency hidden under the k-loop)
            int po0 = post[rowA0 * NN + t]; int tg0 = po0 < 0 ? 0 : po0;
            int po1 = post[rowA1 * NN + t]; int tg1 = po1 < 0 ? 0 : po1;
            size_t f0 = ((size_t)rowA0 * NN + tg0) * 1024 + u;
            size_t f1 = ((size_t)rowA1 * NN + tg1) * 1024 + u;
            float fi0 = g_fiou[f0 + 256], fo0 = g_fiou[f0 + 512], fu0 = g_fiou[f0 + 768];
            float fi1 = g_fiou[f1 + 256], fo1 = g_fiou[f1 + 512], fu1 = g_fiou[f1 + 768];
            float gc0 = __ldcg(&g_gcs[((size_t)rowA0 * NN + tg0) * UU + u]);
            float gc1 = __ldcg(&g_gcs[((size_t)rowA1 * NN + tg1) * UU + u]);

            // Gather csh rows for targets: 32 rows x 256 k, coalesced ldcg
            {
                int r = tid >> 3, q = tid & 7;
                int po = post[(bA0 + r) * NN + t];
                int tg = po < 0 ? 0 : po;
                const float4* src =
                    (const float4*)&g_csh[(((size_t)(bA0 + r)) * NN + tg) * UU];
#pragma unroll
                for (int j = 0; j < 8; ++j) {
                    float4 v = __ldcg(&src[q + j * 8]);
                    *(float4*)&As[r * 260 + (q + j * 8) * 4] = v;
                }
            }

            float aI0 = 0.f, aO0 = 0.f, aU0 = 0.f;
            float aI1 = 0.f, aO1 = 0.f, aU1 = 0.f;
            const float* As0 = &As[(ty * 2) * 260];
            const float* As1 = As0 + 260;

            for (int kc = 0; kc < 256; kc += 64) {
                __syncthreads();
                // Ws chunk: 64 k-rows x (3 gates x 16 units)
#pragma unroll
                for (int j = 0; j < 3; ++j) {
                    int f4 = tid + j * 256;          // 0..767
                    int kk = f4 / 12, c4 = f4 % 12;
                    int gate = c4 >> 2;
                    int ul = (c4 & 3) * 4;
                    *(float4*)&Ws[kk * 48 + gate * 16 + ul] =
                        *(const float4*)&hiou[(size_t)(kc + kk) * 768 +
                                              gate * 256 + uA0 + ul];
                }
                __syncthreads();
#pragma unroll 8
                for (int k = 0; k < 64; ++k) {
                    float a0 = As0[kc + k];
                    float a1 = As1[kc + k];
                    float wi = Ws[k * 48 + tx];
                    float wo = Ws[k * 48 + 16 + tx];
                    float wu = Ws[k * 48 + 32 + tx];
                    aI0 += a0 * wi; aO0 += a0 * wo; aU0 += a0 * wu;
                    aI1 += a1 * wi; aO1 += a1 * wo; aU1 += a1 * wu;
                }
            }

            float mem0 = sigm_(aI0 + fi0) * tanh_(aU0 + fu0) + gc0;
            float mem1 = sigm_(aI1 + fi1) * tanh_(aU1 + fu1) + gc1;
            float out0 = sigm_(aO0 + fo0) * tanh_(mem0);
            float out1 = sigm_(aO1 + fo1) * tanh_(mem1);
            g_out[rowA0 * UU + u] = out0;
            g_mem[rowA0 * UU + u] = mem0;
            g_out[rowA1 * UU + u] = out1;
            g_mem[rowA1 * UU + u] = mem1;
        }
        gsync();

        // ================= Phase C: GEMM2 + gated scatter =================
        {
            const int b  = bC0 + ty;          // one row per thread
            const int cc = cC0 + tx * 2;      // two cols per thread

            int po = post[b * NN + t];
            int om = po >= 0;
            int tg = om ? po : 0;
            int pr = parents[b * NN + tg];
            int pm = om && (pr >= 0);
            int pa = pr < 0 ? 0 : pr;

            // Prefetch scatter operands (overlap with GEMM below)
            float2 fx    = *(const float2*)&g_fiou[((size_t)b * NN + pa) * 1024 + cc];
            float2 csh_o = *(const float2*)&g_csh[((size_t)b * NN + pa) * UU + cc];
            float2 gcs_o = *(const float2*)&g_gcs[((size_t)b * NN + pa) * UU + cc];
            float2 mm    = __ldcg((const float2*)&g_mem[b * UU + cc]);

            // Load out rows (16 rows x 256 k) into smem
#pragma unroll
            for (int j = 0; j < 4; ++j) {
                int f4 = tid + j * 256;
                int r = f4 >> 6, q = f4 & 63;
                float4 v = __ldcg((const float4*)&g_out[(bC0 + r) * UU + q * 4]);
                *(float4*)&outS[r * 260 + q * 4] = v;
            }

            float accx = 0.f, accy = 0.f;
            const float* myOut = &outS[ty * 260];

            for (int kc = 0; kc < 256; kc += 64) {
                __syncthreads();
#pragma unroll
                for (int j = 0; j < 2; ++j) {
                    int f4 = tid + j * 256;
                    int kk = f4 >> 3, q = f4 & 7;
                    *(float4*)&hfS[kk * 36 + q * 4] =
                        *(const float4*)&hf[(size_t)(kc + kk) * UU + cC0 + q * 4];
                }
                __syncthreads();
#pragma unroll 8
                for (int k = 0; k < 64; ++k) {
                    float a = myOut[kc + k];
                    float2 w = *(float2*)&hfS[k * 36 + tx * 2];
                    accx += a * w.x;
                    accy += a * w.y;
                }
            }

            float2 outv = *(float2*)&myOut[cc];
            float gx = sigm_(accx + fx.x) * mm.x;
            float gy = sigm_(accy + fx.y) * mm.y;
            if (pm) {
                *(float2*)&g_csh[((size_t)b * NN + pa) * UU + cc] =
                    make_float2(csh_o.x + outv.x, csh_o.y + outv.y);
                *(float2*)&g_gcs[((size_t)b * NN + pa) * UU + cc] =
                    make_float2(gcs_o.x + gx, gcs_o.y + gy);
            }
            if (om) {
                *(float2*)&hs[((size_t)b * NN + tg) * UU + cc] = outv;
            }
        }
        gsync();
    }
}

// ---------------------------------------------------------------------------
// Launch: 3 graph nodes.
// ---------------------------------------------------------------------------
extern "C" void kernel_launch(void* const* d_in, const int* in_sizes, int n_in,
                              void* d_out, int out_size)
{
    const float* inputs  = (const float*)d_in[0];
    const int*   parents = (const int*)  d_in[1];
    const int*   post    = (const int*)  d_in[2];
    const float* xf      = (const float*)d_in[3];
    const float* hfk     = (const float*)d_in[4];
    const float* hiou    = (const float*)d_in[5];
    const float* bias    = (const float*)d_in[6];
    float* hs = (float*)d_out;

    (void)in_sizes; (void)n_in; (void)out_size;

    k_zero<<<2048, 256>>>((float4*)hs);
    k_precompute<<<dim3(16, 512), 256>>>(inputs, xf, bias);
    k_recur<<<128, 256>>>(parents, post, hfk, hiou, hs);
}

// round 9
// speedup vs baseline: 1.7706x; 1.1652x over previous
#include <cuda_runtime.h>
#include <math.h>

#define BB 256
#define NN 256
#define DD 256
#define UU 256

// ---------------------------------------------------------------------------
// Scratch (static __device__ arrays; no allocations allowed)
// ---------------------------------------------------------------------------
__device__ float g_fiou[(size_t)BB * NN * 1024];  // [b][n][1024]: 0..255=f, 256..511=i, 512..767=o, 768..1023=u
__device__ float g_csh[(size_t)BB * NN * UU];     // child-sum of hidden
__device__ float g_gcs[(size_t)BB * NN * UU];     // gated child cell sum
__device__ float g_out[BB * UU];                  // out for current step
__device__ float g_mem[BB * UU];                  // mem for current step

__device__ unsigned g_count = 0;
__device__ volatile unsigned g_gen = 0;

// Fast transcendentals: __expf rel-err ~2^-21, far inside the 1e-3 budget.
__device__ __forceinline__ float sigm_(float x) {
    return __fdividef(1.f, 1.f + __expf(-x));
}
__device__ __forceinline__ float tanh_(float x) {
    x = fminf(fmaxf(x, -15.f), 15.f);   // avoid inf/inf; tanh saturates anyway
    float e = __expf(2.f * x);
    return __fdividef(e - 1.f, e + 1.f);
}

// Grid-wide sense-reversal barrier; 128 CTAs co-resident (1/SM) so spin is safe.
__device__ __forceinline__ void gsync() {
    __syncthreads();
    if (threadIdx.x == 0) {
        unsigned my = g_gen;
        __threadfence();  // release: publish this CTA's global writes to L2
        if (atomicAdd(&g_count, 1u) == gridDim.x - 1) {
            g_count = 0;
            __threadfence();
            g_gen = my + 1;
        } else {
            while (g_gen == my) { }
        }
        __threadfence();  // acquire
    }
    __syncthreads();
}

// ---------------------------------------------------------------------------
// Zero csh, gcs, hs (output is poisoned before every timed replay)
// ---------------------------------------------------------------------------
__global__ void k_zero(float4* __restrict__ hs4) {
    const size_t n4 = ((size_t)BB * NN * UU) / 4;
    float4 z = make_float4(0.f, 0.f, 0.f, 0.f);
    float4* c4 = (float4*)g_csh;
    float4* g4 = (float4*)g_gcs;
    for (size_t i = (size_t)blockIdx.x * blockDim.x + threadIdx.x; i < n4;
         i += (size_t)gridDim.x * blockDim.x) {
        c4[i] = z; g4[i] = z; hs4[i] = z;
    }
}

// ---------------------------------------------------------------------------
// Precompute: g_fiou = inputs @ x_fiou + bias   (fp32 FFMA roofline)
// ---------------------------------------------------------------------------
__global__ void __launch_bounds__(256, 2) k_precompute(
    const float* __restrict__ X, const float* __restrict__ W,
    const float* __restrict__ bias)
{
    __shared__ float As[16 * 132];
    __shared__ float Ws[16 * 64];
    const int tid = threadIdx.x;
    const int ty  = tid >> 4;
    const int tx  = tid & 15;
    const int m0  = blockIdx.y * 128;
    const int n0  = blockIdx.x * 64;

    float acc[8][4];
#pragma unroll
    for (int i = 0; i < 8; ++i)
#pragma unroll
        for (int j = 0; j < 4; ++j) acc[i][j] = 0.f;

    for (int kc = 0; kc < DD; kc += 16) {
#pragma unroll
        for (int it = 0; it < 2; ++it) {
            int v = tid + it * 256;
            int r = v >> 2, q = v & 3;
            float4 a = *(const float4*)&X[(size_t)(m0 + r) * DD + kc + q * 4];
            As[(q * 4 + 0) * 132 + r] = a.x;
            As[(q * 4 + 1) * 132 + r] = a.y;
            As[(q * 4 + 2) * 132 + r] = a.z;
            As[(q * 4 + 3) * 132 + r] = a.w;
        }
        {
            int kk = tid >> 4, c4 = tid & 15;
            *(float4*)&Ws[kk * 64 + c4 * 4] =
                *(const float4*)&W[(size_t)(kc + kk) * 1024 + n0 + c4 * 4];
        }
        __syncthreads();
#pragma unroll
        for (int k = 0; k < 16; ++k) {
            float4 w  = *(const float4*)&Ws[k * 64 + tx * 4];
            float4 a0 = *(const float4*)&As[k * 132 + ty * 8];
            float4 a1 = *(const float4*)&As[k * 132 + ty * 8 + 4];
            float ar[8] = {a0.x, a0.y, a0.z, a0.w, a1.x, a1.y, a1.z, a1.w};
            float wr[4] = {w.x, w.y, w.z, w.w};
#pragma unroll
            for (int i = 0; i < 8; ++i)
#pragma unroll
                for (int j = 0; j < 4; ++j) acc[i][j] += ar[i] * wr[j];
        }
        __syncthreads();
    }
    float4 bv = *(const float4*)&bias[n0 + tx * 4];
#pragma unroll
    for (int i = 0; i < 8; ++i) {
        float4 o = make_float4(acc[i][0] + bv.x, acc[i][1] + bv.y,
                               acc[i][2] + bv.z, acc[i][3] + bv.w);
        *(float4*)&g_fiou[(size_t)(m0 + ty * 8 + i) * 1024 + n0 + tx * 4] = o;
    }
}

// ---------------------------------------------------------------------------
// Persistent recurrence: 128 CTAs x 256 threads, 256 steps, 2 phases/step.
// Weights (h_iou slice 49KB + h_f slice 37KB) live in SMEM for all 256 steps.
// Dynamic smem layout (floats):
//   [0      , 12288) WsF : h_iou slice [256 k][48 = 3 gates x 16 units]
//   [12288  , 21504) hfF : h_f  slice [256 k][36 = 32 cols + pad]
//   [21504  , 29824) As  : csh gather [32 rows][260]
//   [29824  , 33984) outS: out rows   [16 rows][260]
// Total 135.9 KB (< 227 KB/SM).
// ---------------------------------------------------------------------------
__global__ void __launch_bounds__(256, 1) k_recur(
    const int*   __restrict__ parents,
    const int*   __restrict__ post,
    const float* __restrict__ hf,
    const float* __restrict__ hiou,
    float*       __restrict__ hs)
{
    extern __shared__ __align__(16) float sm[];
    float* WsF  = sm;              // [256][48]
    float* hfF  = sm + 12288;      // [256][36]
    float* As   = sm + 21504;      // [32][260]
    float* outS = sm + 29824;      // [16][260]

    const int c   = blockIdx.x;
    const int tid = threadIdx.x;
    const int tx  = tid & 15;
    const int ty  = tid >> 4;

    // Phase A tiling: 8 b-tiles(32) x 16 u-tiles(16)
    const int bA0 = (c & 7) * 32;
    const int uA0 = (c >> 3) * 16;
    // Phase C tiling: 16 b-tiles(16) x 8 col-tiles(32)
    const int bC0 = (c & 15) * 16;
    const int cC0 = (c >> 4) * 32;

    // ---- One-time weight staging ----
    // h_iou slice: 256 k x (3 gates x 16 units) for this CTA's u-tile
    {
        // 768 float4 total; 3 per thread
#pragma unroll
        for (int j = 0; j < 3; ++j) {
            int f4 = tid + j * 256;          // 0..767
            int kk = f4 / 3, c4 = f4 % 3;    // c4 = gate, 16 floats each
            *(float4*)&WsF[kk * 48 + c4 * 16 + ((tid * 7) & 0)] = // plain layout
                *(const float4*)&hiou[(size_t)kk * 768 + c4 * 256 + uA0];
            // NOTE: float4 covers units [0..3] only; handled below instead.
        }
    }
    __syncthreads();
    // The float4 trick above only staged 4 of 16 units; redo cleanly (scalar-safe):
    for (int idx = tid; idx < 256 * 48; idx += 256) {
        int kk = idx / 48, rem = idx % 48;
        int gate = rem / 16, ul = rem % 16;
        WsF[kk * 48 + gate * 16 + ul] =
            hiou[(size_t)kk * 768 + gate * 256 + uA0 + ul];
    }
    // h_f slice: 256 k x 32 cols (stride 36)
    for (int idx = tid; idx < 256 * 32; idx += 256) {
        int kk = idx >> 5, cl = idx & 31;
        hfF[kk * 36 + cl] = hf[(size_t)kk * UU + cC0 + cl];
    }
    __syncthreads();

    for (int t = 0; t < NN; ++t) {
        // ================= Phase A: GEMM1 + gates =================
        {
            const int rowA0 = bA0 + ty * 2;
            const int rowA1 = rowA0 + 1;
            const int u     = uA0 + tx;

            // Prefetch gate operands (latency hidden under k-loop)
            int po0 = post[rowA0 * NN + t]; int tg0 = po0 < 0 ? 0 : po0;
            int po1 = post[rowA1 * NN + t]; int tg1 = po1 < 0 ? 0 : po1;
            size_t f0 = ((size_t)rowA0 * NN + tg0) * 1024 + u;
            size_t f1 = ((size_t)rowA1 * NN + tg1) * 1024 + u;
            float fi0 = g_fiou[f0 + 256], fo0 = g_fiou[f0 + 512], fu0 = g_fiou[f0 + 768];
            float fi1 = g_fiou[f1 + 256], fo1 = g_fiou[f1 + 512], fu1 = g_fiou[f1 + 768];
            float gc0 = __ldcg(&g_gcs[((size_t)rowA0 * NN + tg0) * UU + u]);
            float gc1 = __ldcg(&g_gcs[((size_t)rowA1 * NN + tg1) * UU + u]);

            // Gather csh rows for targets: 32 rows x 256 k, coalesced ldcg
            {
                int r = tid >> 3, q = tid & 7;
                int po = post[(bA0 + r) * NN + t];
                int tg = po < 0 ? 0 : po;
                const float4* src =
                    (const float4*)&g_csh[(((size_t)(bA0 + r)) * NN + tg) * UU];
#pragma unroll
                for (int j = 0; j < 8; ++j) {
                    float4 v = __ldcg(&src[q + j * 8]);
                    *(float4*)&As[r * 260 + (q + j * 8) * 4] = v;
                }
            }
            __syncthreads();

            float aI0 = 0.f, aO0 = 0.f, aU0 = 0.f;
            float aI1 = 0.f, aO1 = 0.f, aU1 = 0.f;
            const float* As0 = &As[(ty * 2) * 260];
            const float* As1 = As0 + 260;

#pragma unroll 8
            for (int k = 0; k < 256; ++k) {
                float a0 = As0[k];
                float a1 = As1[k];
                float wi = WsF[k * 48 + tx];
                float wo = WsF[k * 48 + 16 + tx];
                float wu = WsF[k * 48 + 32 + tx];
                aI0 += a0 * wi; aO0 += a0 * wo; aU0 += a0 * wu;
                aI1 += a1 * wi; aO1 += a1 * wo; aU1 += a1 * wu;
            }

            float mem0 = sigm_(aI0 + fi0) * tanh_(aU0 + fu0) + gc0;
            float mem1 = sigm_(aI1 + fi1) * tanh_(aU1 + fu1) + gc1;
            float out0 = sigm_(aO0 + fo0) * tanh_(mem0);
            float out1 = sigm_(aO1 + fo1) * tanh_(mem1);
            g_out[rowA0 * UU + u] = out0;
            g_mem[rowA0 * UU + u] = mem0;
            g_out[rowA1 * UU + u] = out1;
            g_mem[rowA1 * UU + u] = mem1;
        }
        gsync();

        // ================= Phase C: GEMM2 + gated scatter =================
        {
            const int b  = bC0 + ty;          // one row per thread
            const int cc = cC0 + tx * 2;      // two cols per thread

            int po = post[b * NN + t];
            int om = po >= 0;
            int tg = om ? po : 0;
            int pr = parents[b * NN + tg];
            int pm = om && (pr >= 0);
            int pa = pr < 0 ? 0 : pr;

            // Prefetch scatter operands (overlap with GEMM below)
            float2 fx    = *(const float2*)&g_fiou[((size_t)b * NN + pa) * 1024 + cc];
            float2 csh_o = *(const float2*)&g_csh[((size_t)b * NN + pa) * UU + cc];
            float2 gcs_o = *(const float2*)&g_gcs[((size_t)b * NN + pa) * UU + cc];
            float2 mm    = __ldcg((const float2*)&g_mem[b * UU + cc]);

            // Load out rows (16 rows x 256 k) into smem
#pragma unroll
            for (int j = 0; j < 4; ++j) {
                int f4 = tid + j * 256;
                int r = f4 >> 6, q = f4 & 63;
                float4 v = __ldcg((const float4*)&g_out[(bC0 + r) * UU + q * 4]);
                *(float4*)&outS[r * 260 + q * 4] = v;
            }
            __syncthreads();

            float accx = 0.f, accy = 0.f;
            const float* myOut = &outS[ty * 260];

#pragma unroll 8
            for (int k = 0; k < 256; ++k) {
                float a = myOut[k];
                float2 w = *(float2*)&hfF[k * 36 + tx * 2];
                accx += a * w.x;
                accy += a * w.y;
            }

            float2 outv = *(float2*)&myOut[cc];
            float gx = sigm_(accx + fx.x) * mm.x;
            float gy = sigm_(accy + fx.y) * mm.y;
            if (pm) {
                *(float2*)&g_csh[((size_t)b * NN + pa) * UU + cc] =
                    make_float2(csh_o.x + outv.x, csh_o.y + outv.y);
                *(float2*)&g_gcs[((size_t)b * NN + pa) * UU + cc] =
                    make_float2(gcs_o.x + gx, gcs_o.y + gy);
            }
            if (om) {
                *(float2*)&hs[((size_t)b * NN + tg) * UU + cc] = outv;
            }
        }
        gsync();
    }
}

// ---------------------------------------------------------------------------
// Launch: 3 graph nodes. Dynamic smem for k_recur is 135.9 KB.
// ---------------------------------------------------------------------------
extern "C" void kernel_launch(void* const* d_in, const int* in_sizes, int n_in,
                              void* d_out, int out_size)
{
    const float* inputs  = (const float*)d_in[0];
    const int*   parents = (const int*)  d_in[1];
    const int*   post    = (const int*)  d_in[2];
    const float* xf      = (const float*)d_in[3];
    const float* hfk     = (const float*)d_in[4];
    const float* hiou    = (const float*)d_in[5];
    const float* bias    = (const float*)d_in[6];
    float* hs = (float*)d_out;

    (void)in_sizes; (void)n_in; (void)out_size;

    static int smem_set = 0;
    const int SMEM_BYTES = 33984 * 4;
    if (!smem_set) {
        cudaFuncSetAttribute(k_recur, cudaFuncAttributeMaxDynamicSharedMemorySize,
                             SMEM_BYTES);
        smem_set = 1;
    }

    k_zero<<<2048, 256>>>((float4*)hs);
    k_precompute<<<dim3(16, 512), 256>>>(inputs, xf, bias);
    k_recur<<<128, 256, SMEM_BYTES>>>(parents, post, hfk, hiou, hs);
}

// round 10
// speedup vs baseline: 2.1170x; 1.1956x over previous
#include <cuda_runtime.h>
#include <math.h>

#define BB 256
#define NN 256
#define DD 256
#define UU 256

// ---------------------------------------------------------------------------
// Scratch (static __device__ arrays; no allocations allowed)
// ---------------------------------------------------------------------------
__device__ float g_fiou[(size_t)BB * NN * 1024];  // [b][n][1024]: 0..255=f, 256..511=i, 512..767=o, 768..1023=u
__device__ float g_csh[(size_t)BB * NN * UU];     // child-sum of hidden
__device__ float g_gcs[(size_t)BB * NN * UU];     // gated child cell sum
__device__ float g_out[BB * UU];                  // out for current step
__device__ float g_mem[BB * UU];                  // mem for current step

__device__ unsigned g_count = 0;
__device__ volatile unsigned g_gen = 0;

// Fast transcendentals: __expf rel-err ~2^-21, far inside the 1e-3 budget.
__device__ __forceinline__ float sigm_(float x) {
    return __fdividef(1.f, 1.f + __expf(-x));
}
__device__ __forceinline__ float tanh_(float x) {
    x = fminf(fmaxf(x, -15.f), 15.f);
    float e = __expf(2.f * x);
    return __fdividef(e - 1.f, e + 1.f);
}

// Grid-wide sense-reversal barrier; 128 CTAs co-resident (1/SM) so spin is safe.
__device__ __forceinline__ void gsync() {
    __syncthreads();
    if (threadIdx.x == 0) {
        unsigned my = g_gen;
        __threadfence();  // release: publish this CTA's global writes to L2
        if (atomicAdd(&g_count, 1u) == gridDim.x - 1) {
            g_count = 0;
            __threadfence();
            g_gen = my + 1;
        } else {
            while (g_gen == my) { }
        }
        __threadfence();  // acquire
    }
    __syncthreads();
}

// ---------------------------------------------------------------------------
// Zero csh, gcs, hs (output is poisoned before every timed replay)
// ---------------------------------------------------------------------------
__global__ void k_zero(float4* __restrict__ hs4) {
    const size_t n4 = ((size_t)BB * NN * UU) / 4;
    float4 z = make_float4(0.f, 0.f, 0.f, 0.f);
    float4* c4 = (float4*)g_csh;
    float4* g4 = (float4*)g_gcs;
    for (size_t i = (size_t)blockIdx.x * blockDim.x + threadIdx.x; i < n4;
         i += (size_t)gridDim.x * blockDim.x) {
        c4[i] = z; g4[i] = z; hs4[i] = z;
    }
}

// ---------------------------------------------------------------------------
// Precompute: g_fiou = inputs @ x_fiou + bias   (fp32 FFMA roofline)
// ---------------------------------------------------------------------------
__global__ void __launch_bounds__(256, 2) k_precompute(
    const float* __restrict__ X, const float* __restrict__ W,
    const float* __restrict__ bias)
{
    __shared__ float As[16 * 132];
    __shared__ float Ws[16 * 64];
    const int tid = threadIdx.x;
    const int ty  = tid >> 4;
    const int tx  = tid & 15;
    const int m0  = blockIdx.y * 128;
    const int n0  = blockIdx.x * 64;

    float acc[8][4];
#pragma unroll
    for (int i = 0; i < 8; ++i)
#pragma unroll
        for (int j = 0; j < 4; ++j) acc[i][j] = 0.f;

    for (int kc = 0; kc < DD; kc += 16) {
#pragma unroll
        for (int it = 0; it < 2; ++it) {
            int v = tid + it * 256;
            int r = v >> 2, q = v & 3;
            float4 a = *(const float4*)&X[(size_t)(m0 + r) * DD + kc + q * 4];
            As[(q * 4 + 0) * 132 + r] = a.x;
            As[(q * 4 + 1) * 132 + r] = a.y;
            As[(q * 4 + 2) * 132 + r] = a.z;
            As[(q * 4 + 3) * 132 + r] = a.w;
        }
        {
            int kk = tid >> 4, c4 = tid & 15;
            *(float4*)&Ws[kk * 64 + c4 * 4] =
                *(const float4*)&W[(size_t)(kc + kk) * 1024 + n0 + c4 * 4];
        }
        __syncthreads();
#pragma unroll
        for (int k = 0; k < 16; ++k) {
            float4 w  = *(const float4*)&Ws[k * 64 + tx * 4];
            float4 a0 = *(const float4*)&As[k * 132 + ty * 8];
            float4 a1 = *(const float4*)&As[k * 132 + ty * 8 + 4];
            float ar[8] = {a0.x, a0.y, a0.z, a0.w, a1.x, a1.y, a1.z, a1.w};
            float wr[4] = {w.x, w.y, w.z, w.w};
#pragma unroll
            for (int i = 0; i < 8; ++i)
#pragma unroll
                for (int j = 0; j < 4; ++j) acc[i][j] += ar[i] * wr[j];
        }
        __syncthreads();
    }
    float4 bv = *(const float4*)&bias[n0 + tx * 4];
#pragma unroll
    for (int i = 0; i < 8; ++i) {
        float4 o = make_float4(acc[i][0] + bv.x, acc[i][1] + bv.y,
                               acc[i][2] + bv.z, acc[i][3] + bv.w);
        *(float4*)&g_fiou[(size_t)(m0 + ty * 8 + i) * 1024 + n0 + tx * 4] = o;
    }
}

// ---------------------------------------------------------------------------
// Persistent recurrence: 128 CTAs x 256 threads, 256 steps, 2 phases/step.
// Intra-CTA K-split (4 slices x 64 threads) raises register blocking so both
// GEMMs run at (or near) the FMA pipe floor instead of the smem-BW bound.
// Dynamic smem (floats):
//   [0     ,12288) WsF : h_iou slice [256 k][48]       (resident all steps)
//   [12288 ,21504) hfF : h_f  slice [256 k][36]        (resident all steps)
//   [21504 ,29952) AsT : csh gather, k-major [256 k][33]
//   [29952 ,34112) outS: out rows [16][260]
//   [34112 ,40512) red : cross-slice partials (A: 64*4*25; C aliases 64*4*9)
// Total 162.0 KB.
// ---------------------------------------------------------------------------
__global__ void __launch_bounds__(256, 1) k_recur(
    const int*   __restrict__ parents,
    const int*   __restrict__ post,
    const float* __restrict__ hf,
    const float* __restrict__ hiou,
    float*       __restrict__ hs)
{
    extern __shared__ __align__(16) float sm[];
    float* WsF  = sm;              // [256][48]
    float* hfF  = sm + 12288;      // [256][36]
    float* AsT  = sm + 21504;      // [256][33]  k-major
    float* outS = sm + 29952;      // [16][260]
    float* red  = sm + 34112;      // A: [4*64][25] ; C: [4*64][9]

    const int c   = blockIdx.x;
    const int tid = threadIdx.x;
    const int tx  = tid & 15;
    const int ty  = tid >> 4;

    // Phase A tiling: 8 b-tiles(32 rows) x 16 u-tiles(16 units x 3 gates)
    const int bA0 = (c & 7) * 32;
    const int uA0 = (c >> 3) * 16;
    // Phase C tiling: 16 b-tiles(16 rows) x 8 col-tiles(32 cols)
    const int bC0 = (c & 15) * 16;
    const int cC0 = (c >> 4) * 32;

    // K-split decomposition (both phases): slice s, local l
    const int sK = tid >> 6;       // 0..3 -> k in [sK*64, sK*64+64)
    const int lK = tid & 63;
    const int rgA = lK >> 3;       // rows bA0 + rgA*4 .. +3
    const int cgA = lK & 7;        // units cgA*2, cgA*2+1 (x 3 gates)
    const int rgC = lK >> 3;       // rows bC0 + rgC*2, +1
    const int cgC = lK & 7;        // cols cC0 + cgC*4 .. +3
    const int k0  = sK * 64;

    // ---- One-time weight staging (resident across all 256 steps) ----
    for (int idx = tid; idx < 256 * 48; idx += 256) {
        int kk = idx / 48, rem = idx % 48;
        int gate = rem / 16, ul = rem % 16;
        WsF[kk * 48 + gate * 16 + ul] =
            hiou[(size_t)kk * 768 + gate * 256 + uA0 + ul];
    }
    for (int idx = tid; idx < 256 * 32; idx += 256) {
        int kk = idx >> 5, cl = idx & 31;
        hfF[kk * 36 + cl] = hf[(size_t)kk * UU + cC0 + cl];
    }
    __syncthreads();

    for (int t = 0; t < NN; ++t) {
        // ================= Phase A: GEMM1 (k-split 4) + gates =================
        {
            // Gate-consumer prefetch (rows ty*2, ty*2+1; unit uA0+tx)
            const int rowA0 = bA0 + ty * 2;
            const int rowA1 = rowA0 + 1;
            const int u     = uA0 + tx;
            int po0 = post[rowA0 * NN + t]; int tg0 = po0 < 0 ? 0 : po0;
            int po1 = post[rowA1 * NN + t]; int tg1 = po1 < 0 ? 0 : po1;
            size_t f0 = ((size_t)rowA0 * NN + tg0) * 1024 + u;
            size_t f1 = ((size_t)rowA1 * NN + tg1) * 1024 + u;
            float fi0 = g_fiou[f0 + 256], fo0 = g_fiou[f0 + 512], fu0 = g_fiou[f0 + 768];
            float fi1 = g_fiou[f1 + 256], fo1 = g_fiou[f1 + 512], fu1 = g_fiou[f1 + 768];
            float gc0 = __ldcg(&g_gcs[((size_t)rowA0 * NN + tg0) * UU + u]);
            float gc1 = __ldcg(&g_gcs[((size_t)rowA1 * NN + tg1) * UU + u]);

            // Gather csh rows -> AsT (k-major, stride 33; conflict-free)
            {
                int r = tid >> 3, q = tid & 7;   // 8 lanes per row: coalesced LDG
                int po = post[(bA0 + r) * NN + t];
                int tg = po < 0 ? 0 : po;
                const float4* src =
                    (const float4*)&g_csh[(((size_t)(bA0 + r)) * NN + tg) * UU];
#pragma unroll
                for (int j = 0; j < 8; ++j) {
                    float4 v = __ldcg(&src[q + j * 8]);
                    int ks = (q + j * 8) * 4;
                    AsT[(ks + 0) * 33 + r] = v.x;
                    AsT[(ks + 1) * 33 + r] = v.y;
                    AsT[(ks + 2) * 33 + r] = v.z;
                    AsT[(ks + 3) * 33 + r] = v.w;
                }
            }
            __syncthreads();

            // k-slice accumulate: 4 rows x (2 units x 3 gates) = 24 acc
            float acc[4][6];
#pragma unroll
            for (int i = 0; i < 4; ++i)
#pragma unroll
                for (int j = 0; j < 6; ++j) acc[i][j] = 0.f;

#pragma unroll 4
            for (int k = 0; k < 64; ++k) {
                const int kk = k0 + k;
                const float* ap = &AsT[kk * 33 + rgA * 4];
                const float* wp = &WsF[kk * 48 + cgA * 2];
                float a0 = ap[0], a1 = ap[1], a2 = ap[2], a3 = ap[3];
                float wi0 = wp[0],  wi1 = wp[1];
                float wo0 = wp[16], wo1 = wp[17];
                float wu0 = wp[32], wu1 = wp[33];
                acc[0][0] += a0 * wi0; acc[0][1] += a0 * wi1;
                acc[0][2] += a0 * wo0; acc[0][3] += a0 * wo1;
                acc[0][4] += a0 * wu0; acc[0][5] += a0 * wu1;
                acc[1][0] += a1 * wi0; acc[1][1] += a1 * wi1;
                acc[1][2] += a1 * wo0; acc[1][3] += a1 * wo1;
                acc[1][4] += a1 * wu0; acc[1][5] += a1 * wu1;
                acc[2][0] += a2 * wi0; acc[2][1] += a2 * wi1;
                acc[2][2] += a2 * wo0; acc[2][3] += a2 * wo1;
                acc[2][4] += a2 * wu0; acc[2][5] += a2 * wu1;
                acc[3][0] += a3 * wi0; acc[3][1] += a3 * wi1;
                acc[3][2] += a3 * wo0; acc[3][3] += a3 * wo1;
                acc[3][4] += a3 * wu0; acc[3][5] += a3 * wu1;
            }
            // Partials -> red[(s*64+l)*25 + i*6 + gj]  (stride 25: conflict-free)
            {
                float* rp = &red[tid * 25];
#pragma unroll
                for (int i = 0; i < 4; ++i)
#pragma unroll
                    for (int j = 0; j < 6; ++j) rp[i * 6 + j] = acc[i][j];
            }
            __syncthreads();

            // Reduce 4 slices + gates (rows ty*2+jr, unit uA0+tx)
            const int cg = tx >> 1, jj = tx & 1;
            float memv[2], outv[2];
#pragma unroll
            for (int jr = 0; jr < 2; ++jr) {
                int r = ty * 2 + jr;
                int base = ((r >> 2) * 8 + cg) * 25 + (r & 3) * 6 + jj;
                float aI = red[base] + red[64 * 25 + base] +
                           red[128 * 25 + base] + red[192 * 25 + base];
                float aO = red[base + 2] + red[64 * 25 + base + 2] +
                           red[128 * 25 + base + 2] + red[192 * 25 + base + 2];
                float aU = red[base + 4] + red[64 * 25 + base + 4] +
                           red[128 * 25 + base + 4] + red[192 * 25 + base + 4];
                float fi = jr ? fi1 : fi0, fo = jr ? fo1 : fo0;
                float fu = jr ? fu1 : fu0, gc = jr ? gc1 : gc0;
                memv[jr] = sigm_(aI + fi) * tanh_(aU + fu) + gc;
                outv[jr] = sigm_(aO + fo) * tanh_(memv[jr]);
            }
            g_out[rowA0 * UU + u] = outv[0];
            g_mem[rowA0 * UU + u] = memv[0];
            g_out[rowA1 * UU + u] = outv[1];
            g_mem[rowA1 * UU + u] = memv[1];
        }
        gsync();

        // ================= Phase C: GEMM2 (k-split 4) + gated scatter =========
        {
            // Scatter-consumer prefetch (row bC0+ty, cols cC0+tx*2..+1)
            const int b  = bC0 + ty;
            const int cc = cC0 + tx * 2;
            int po = post[b * NN + t];
            int om = po >= 0;
            int tg = om ? po : 0;
            int pr = parents[b * NN + tg];
            int pm = om && (pr >= 0);
            int pa = pr < 0 ? 0 : pr;
            float2 fx    = *(const float2*)&g_fiou[((size_t)b * NN + pa) * 1024 + cc];
            float2 csh_o = *(const float2*)&g_csh[((size_t)b * NN + pa) * UU + cc];
            float2 gcs_o = *(const float2*)&g_gcs[((size_t)b * NN + pa) * UU + cc];
            float2 mm    = __ldcg((const float2*)&g_mem[b * UU + cc]);

            // Load out rows (16 x 256) into smem
#pragma unroll
            for (int j = 0; j < 4; ++j) {
                int f4 = tid + j * 256;
                int r = f4 >> 6, q = f4 & 63;
                float4 v = __ldcg((const float4*)&g_out[(bC0 + r) * UU + q * 4]);
                *(float4*)&outS[r * 260 + q * 4] = v;
            }
            __syncthreads();

            // k-slice accumulate: 2 rows x 4 cols
            float acc[2][4];
#pragma unroll
            for (int i = 0; i < 2; ++i)
#pragma unroll
                for (int j = 0; j < 4; ++j) acc[i][j] = 0.f;

            const float* o0 = &outS[(rgC * 2) * 260 + k0];
            const float* o1 = o0 + 260;
#pragma unroll 4
            for (int k = 0; k < 64; ++k) {
                const float* wp = &hfF[(k0 + k) * 36 + cgC * 4];
                float a0 = o0[k], a1 = o1[k];
                float w0 = wp[0], w1 = wp[1], w2 = wp[2], w3 = wp[3];
                acc[0][0] += a0 * w0; acc[0][1] += a0 * w1;
                acc[0][2] += a0 * w2; acc[0][3] += a0 * w3;
                acc[1][0] += a1 * w0; acc[1][1] += a1 * w1;
                acc[1][2] += a1 * w2; acc[1][3] += a1 * w3;
            }
            {
                float* rp = &red[tid * 9];
#pragma unroll
                for (int i = 0; i < 2; ++i)
#pragma unroll
                    for (int j = 0; j < 4; ++j) rp[i * 4 + j] = acc[i][j];
            }
            __syncthreads();

            // Reduce + gated scatter
            float accv[2];
#pragma unroll
            for (int j = 0; j < 2; ++j) {
                int cl = tx * 2 + j;
                int base = ((ty >> 1) * 8 + (cl >> 2)) * 9 + (ty & 1) * 4 + (cl & 3);
                accv[j] = red[base] + red[64 * 9 + base] +
                          red[128 * 9 + base] + red[192 * 9 + base];
            }
            float2 outp = *(const float2*)&outS[ty * 260 + cc];
            float gx = sigm_(accv[0] + fx.x) * mm.x;
            float gy = sigm_(accv[1] + fx.y) * mm.y;
            if (pm) {
                *(float2*)&g_csh[((size_t)b * NN + pa) * UU + cc] =
                    make_float2(csh_o.x + outp.x, csh_o.y + outp.y);
                *(float2*)&g_gcs[((size_t)b * NN + pa) * UU + cc] =
                    make_float2(gcs_o.x + gx, gcs_o.y + gy);
            }
            if (om) {
                *(float2*)&hs[((size_t)b * NN + tg) * UU + cc] = outp;
            }
        }
        gsync();
    }
}

// ---------------------------------------------------------------------------
// Launch: 3 graph nodes. Dynamic smem for k_recur is 162.0 KB.
// ---------------------------------------------------------------------------
extern "C" void kernel_launch(void* const* d_in, const int* in_sizes, int n_in,
                              void* d_out, int out_size)
{
    const float* inputs  = (const float*)d_in[0];
    const int*   parents = (const int*)  d_in[1];
    const int*   post    = (const int*)  d_in[2];
    const float* xf      = (const float*)d_in[3];
    const float* hfk     = (const float*)d_in[4];
    const float* hiou    = (const float*)d_in[5];
    const float* bias    = (const float*)d_in[6];
    float* hs = (float*)d_out;

    (void)in_sizes; (void)n_in; (void)out_size;

    static int smem_set = 0;
    const int SMEM_BYTES = 40512 * 4;
    if (!smem_set) {
        cudaFuncSetAttribute(k_recur, cudaFuncAttributeMaxDynamicSharedMemorySize,
                             SMEM_BYTES);
        smem_set = 1;
    }

    k_zero<<<2048, 256>>>((float4*)hs);
    k_precompute<<<dim3(16, 512), 256>>>(inputs, xf, bias);
    k_recur<<<128, 256, SMEM_BYTES>>>(parents, post, hfk, hiou, hs);
}

// round 11
// speedup vs baseline: 2.1633x; 1.0219x over previous
#include <cuda_runtime.h>
#include <math.h>

#define BB 256
#define NN 256
#define DD 256
#define UU 256

typedef unsigned long long ull;

// ---------------------------------------------------------------------------
// Packed fp32x2 (Blackwell FFMA2): 2 IEEE fp32 FMAs per instruction.
// ---------------------------------------------------------------------------
__device__ __forceinline__ void ffma2(ull& d, ull a, ull b) {
    asm("fma.rn.f32x2 %0, %1, %2, %0;" : "+l"(d) : "l"(a), "l"(b));
}
__device__ __forceinline__ ull pack2(float x, float y) {
    ull r;
    asm("mov.b64 %0, {%1, %2};"
        : "=l"(r) : "r"(__float_as_uint(x)), "r"(__float_as_uint(y)));
    return r;
}
__device__ __forceinline__ float2 unpack2(ull v) {
    unsigned lo, hi;
    asm("mov.b64 {%0, %1}, %2;" : "=r"(lo), "=r"(hi) : "l"(v));
    return make_float2(__uint_as_float(lo), __uint_as_float(hi));
}

// ---------------------------------------------------------------------------
// Scratch (static __device__ arrays; no allocations allowed)
// ---------------------------------------------------------------------------
__device__ float g_fiou[(size_t)BB * NN * 1024];  // [b][n][1024]: 0..255=f, 256..511=i, 512..767=o, 768..1023=u
__device__ float g_csh[(size_t)BB * NN * UU];     // child-sum of hidden
__device__ float g_gcs[(size_t)BB * NN * UU];     // gated child cell sum
__device__ float g_out[BB * UU];                  // out for current step
__device__ float g_mem[BB * UU];                  // mem for current step

__device__ unsigned g_count = 0;
__device__ volatile unsigned g_gen = 0;

// Fast transcendentals: __expf rel-err ~2^-21, far inside the 1e-3 budget.
__device__ __forceinline__ float sigm_(float x) {
    return __fdividef(1.f, 1.f + __expf(-x));
}
__device__ __forceinline__ float tanh_(float x) {
    x = fminf(fmaxf(x, -15.f), 15.f);
    float e = __expf(2.f * x);
    return __fdividef(e - 1.f, e + 1.f);
}

// Grid-wide sense-reversal barrier; 128 CTAs co-resident (1/SM) so spin is safe.
__device__ __forceinline__ void gsync() {
    __syncthreads();
    if (threadIdx.x == 0) {
        unsigned my = g_gen;
        __threadfence();  // release: publish this CTA's global writes to L2
        if (atomicAdd(&g_count, 1u) == gridDim.x - 1) {
            g_count = 0;
            __threadfence();
            g_gen = my + 1;
        } else {
            while (g_gen == my) { }
        }
        __threadfence();  // acquire
    }
    __syncthreads();
}

// ---------------------------------------------------------------------------
// Zero csh, gcs, hs (output is poisoned before every timed replay)
// ---------------------------------------------------------------------------
__global__ void k_zero(float4* __restrict__ hs4) {
    const size_t n4 = ((size_t)BB * NN * UU) / 4;
    float4 z = make_float4(0.f, 0.f, 0.f, 0.f);
    float4* c4 = (float4*)g_csh;
    float4* g4 = (float4*)g_gcs;
    for (size_t i = (size_t)blockIdx.x * blockDim.x + threadIdx.x; i < n4;
         i += (size_t)gridDim.x * blockDim.x) {
        c4[i] = z; g4[i] = z; hs4[i] = z;
    }
}

// ---------------------------------------------------------------------------
// Precompute v2: g_fiou = inputs @ x_fiou + bias, FFMA2 path.
// CTA tile 128x128, thread tile 8x8 (as 8x4 fp32 pairs), K chunks of 16.
// Cols are split tx*4 / 64+tx*4 so LDS stays at the 2-wavefront floor.
// ---------------------------------------------------------------------------
__global__ void __launch_bounds__(256, 2) k_precompute(
    const float* __restrict__ X, const float* __restrict__ W,
    const float* __restrict__ bias)
{
    __shared__ __align__(16) float As[16 * 132];  // [k][row]
    __shared__ __align__(16) float Ws[16 * 132];  // [k][col]
    const int tid = threadIdx.x;
    const int ty  = tid >> 4;
    const int tx  = tid & 15;
    const int m0  = blockIdx.y * 128;
    const int n0  = blockIdx.x * 128;

    ull acc[8][4];   // 8 rows x 4 col-pairs (cols tx*4+{0,1},{2,3}; 64+tx*4+{0,1},{2,3})
#pragma unroll
    for (int i = 0; i < 8; ++i)
#pragma unroll
        for (int j = 0; j < 4; ++j) acc[i][j] = 0ull;

    for (int kc = 0; kc < DD; kc += 16) {
        // A chunk: 128 rows x 16 k, transposed As[k][row]
#pragma unroll
        for (int it = 0; it < 2; ++it) {
            int v = tid + it * 256;
            int r = v >> 2, q = v & 3;
            float4 a = *(const float4*)&X[(size_t)(m0 + r) * DD + kc + q * 4];
            As[(q * 4 + 0) * 132 + r] = a.x;
            As[(q * 4 + 1) * 132 + r] = a.y;
            As[(q * 4 + 2) * 132 + r] = a.z;
            As[(q * 4 + 3) * 132 + r] = a.w;
        }
        // W chunk: 16 k x 128 cols
#pragma unroll
        for (int it = 0; it < 2; ++it) {
            int idx = tid + it * 256;
            int kk = idx >> 5, c4 = idx & 31;
            *(float4*)&Ws[kk * 132 + c4 * 4] =
                *(const float4*)&W[(size_t)(kc + kk) * 1024 + n0 + c4 * 4];
        }
        __syncthreads();
#pragma unroll
        for (int k = 0; k < 16; ++k) {
            float4 a0 = *(const float4*)&As[k * 132 + ty * 4];
            float4 a1 = *(const float4*)&As[k * 132 + 64 + ty * 4];
            ull w00 = *(const ull*)&Ws[k * 132 + tx * 4];
            ull w01 = *(const ull*)&Ws[k * 132 + tx * 4 + 2];
            ull w10 = *(const ull*)&Ws[k * 132 + 64 + tx * 4];
            ull w11 = *(const ull*)&Ws[k * 132 + 64 + tx * 4 + 2];
            float ar[8] = {a0.x, a0.y, a0.z, a0.w, a1.x, a1.y, a1.z, a1.w};
#pragma unroll
            for (int i = 0; i < 8; ++i) {
                ull ap = pack2(ar[i], ar[i]);
                ffma2(acc[i][0], ap, w00);
                ffma2(acc[i][1], ap, w01);
                ffma2(acc[i][2], ap, w10);
                ffma2(acc[i][3], ap, w11);
            }
        }
        __syncthreads();
    }
    float4 bv0 = *(const float4*)&bias[n0 + tx * 4];
    float4 bv1 = *(const float4*)&bias[n0 + 64 + tx * 4];
#pragma unroll
    for (int i = 0; i < 8; ++i) {
        int row = m0 + ((i < 4) ? (ty * 4 + i) : (64 + ty * 4 + (i - 4)));
        float2 p0 = unpack2(acc[i][0]);
        float2 p1 = unpack2(acc[i][1]);
        float2 p2 = unpack2(acc[i][2]);
        float2 p3 = unpack2(acc[i][3]);
        float4 o0 = make_float4(p0.x + bv0.x, p0.y + bv0.y, p1.x + bv0.z, p1.y + bv0.w);
        float4 o1 = make_float4(p2.x + bv1.x, p2.y + bv1.y, p3.x + bv1.z, p3.y + bv1.w);
        *(float4*)&g_fiou[(size_t)row * 1024 + n0 + tx * 4] = o0;
        *(float4*)&g_fiou[(size_t)row * 1024 + n0 + 64 + tx * 4] = o1;
    }
}

// ---------------------------------------------------------------------------
// Persistent recurrence: 128 CTAs x 256 threads, 256 steps, 2 phases/step.
// Intra-CTA K-split (4 slices x 64 threads) + FFMA2 packed accumulators.
// Dynamic smem (floats):
//   [0     ,12288) WsF : h_iou slice [256 k][48]       (resident all steps)
//   [12288 ,21504) hfF : h_f  slice [256 k][36]        (resident all steps)
//   [21504 ,29952) AsT : csh gather, k-major [256 k][33]
//   [29952 ,34112) outS: out rows [16][260]
//   [34112 ,40512) red : cross-slice partials (A: 64*4*25; C aliases 64*4*9)
// Total 162.0 KB.
// ---------------------------------------------------------------------------
__global__ void __launch_bounds__(256, 1) k_recur(
    const int*   __restrict__ parents,
    const int*   __restrict__ post,
    const float* __restrict__ hf,
    const float* __restrict__ hiou,
    float*       __restrict__ hs)
{
    extern __shared__ __align__(16) float sm[];
    float* WsF  = sm;              // [256][48]
    float* hfF  = sm + 12288;      // [256][36]
    float* AsT  = sm + 21504;      // [256][33]  k-major
    float* outS = sm + 29952;      // [16][260]
    float* red  = sm + 34112;      // A: [4*64][25] ; C: [4*64][9]

    const int c   = blockIdx.x;
    const int tid = threadIdx.x;
    const int tx  = tid & 15;
    const int ty  = tid >> 4;

    // Phase A tiling: 8 b-tiles(32 rows) x 16 u-tiles(16 units x 3 gates)
    const int bA0 = (c & 7) * 32;
    const int uA0 = (c >> 3) * 16;
    // Phase C tiling: 16 b-tiles(16 rows) x 8 col-tiles(32 cols)
    const int bC0 = (c & 15) * 16;
    const int cC0 = (c >> 4) * 32;

    // K-split decomposition (both phases): slice sK, local lK
    const int sK = tid >> 6;
    const int lK = tid & 63;
    const int rgA = lK >> 3;       // rows bA0 + rgA*4 .. +3
    const int cgA = lK & 7;        // units cgA*2, cgA*2+1 (x 3 gates)
    const int rgC = lK >> 3;       // rows bC0 + rgC*2, +1
    const int cgC = lK & 7;        // cols cC0 + cgC*4 .. +3
    const int k0  = sK * 64;

    // ---- One-time weight staging (resident across all 256 steps) ----
    for (int idx = tid; idx < 256 * 48; idx += 256) {
        int kk = idx / 48, rem = idx % 48;
        int gate = rem / 16, ul = rem % 16;
        WsF[kk * 48 + gate * 16 + ul] =
            hiou[(size_t)kk * 768 + gate * 256 + uA0 + ul];
    }
    for (int idx = tid; idx < 256 * 32; idx += 256) {
        int kk = idx >> 5, cl = idx & 31;
        hfF[kk * 36 + cl] = hf[(size_t)kk * UU + cC0 + cl];
    }
    __syncthreads();

    for (int t = 0; t < NN; ++t) {
        // ================= Phase A: GEMM1 (k-split 4, FFMA2) + gates =========
        {
            // Gate-consumer prefetch (rows ty*2, ty*2+1; unit uA0+tx)
            const int rowA0 = bA0 + ty * 2;
            const int rowA1 = rowA0 + 1;
            const int u     = uA0 + tx;
            int po0 = post[rowA0 * NN + t]; int tg0 = po0 < 0 ? 0 : po0;
            int po1 = post[rowA1 * NN + t]; int tg1 = po1 < 0 ? 0 : po1;
            size_t f0 = ((size_t)rowA0 * NN + tg0) * 1024 + u;
            size_t f1 = ((size_t)rowA1 * NN + tg1) * 1024 + u;
            float fi0 = g_fiou[f0 + 256], fo0 = g_fiou[f0 + 512], fu0 = g_fiou[f0 + 768];
            float fi1 = g_fiou[f1 + 256], fo1 = g_fiou[f1 + 512], fu1 = g_fiou[f1 + 768];
            float gc0 = __ldcg(&g_gcs[((size_t)rowA0 * NN + tg0) * UU + u]);
            float gc1 = __ldcg(&g_gcs[((size_t)rowA1 * NN + tg1) * UU + u]);

            // Gather csh rows -> AsT (k-major, stride 33; conflict-free)
            {
                int r = tid >> 3, q = tid & 7;
                int po = post[(bA0 + r) * NN + t];
                int tg = po < 0 ? 0 : po;
                const float4* src =
                    (const float4*)&g_csh[(((size_t)(bA0 + r)) * NN + tg) * UU];
#pragma unroll
                for (int j = 0; j < 8; ++j) {
                    float4 v = __ldcg(&src[q + j * 8]);
                    int ks = (q + j * 8) * 4;
                    AsT[(ks + 0) * 33 + r] = v.x;
                    AsT[(ks + 1) * 33 + r] = v.y;
                    AsT[(ks + 2) * 33 + r] = v.z;
                    AsT[(ks + 3) * 33 + r] = v.w;
                }
            }
            __syncthreads();

            // k-slice accumulate: 4 rows x 3 gate-pairs (FFMA2)
            ull accI[4] = {0ull, 0ull, 0ull, 0ull};
            ull accO[4] = {0ull, 0ull, 0ull, 0ull};
            ull accU[4] = {0ull, 0ull, 0ull, 0ull};

#pragma unroll 4
            for (int k = 0; k < 64; ++k) {
                const int kk = k0 + k;
                const float* ap = &AsT[kk * 33 + rgA * 4];
                const float* wp = &WsF[kk * 48 + cgA * 2];
                ull wI = *(const ull*)&wp[0];
                ull wO = *(const ull*)&wp[16];
                ull wU = *(const ull*)&wp[32];
                float a0 = ap[0], a1 = ap[1], a2 = ap[2], a3 = ap[3];
                ull p0 = pack2(a0, a0), p1 = pack2(a1, a1);
                ull p2 = pack2(a2, a2), p3 = pack2(a3, a3);
                ffma2(accI[0], p0, wI); ffma2(accO[0], p0, wO); ffma2(accU[0], p0, wU);
                ffma2(accI[1], p1, wI); ffma2(accO[1], p1, wO); ffma2(accU[1], p1, wU);
                ffma2(accI[2], p2, wI); ffma2(accO[2], p2, wO); ffma2(accU[2], p2, wU);
                ffma2(accI[3], p3, wI); ffma2(accO[3], p3, wO); ffma2(accU[3], p3, wU);
            }
            // Partials -> red[(s*64+l)*25 + i*6 + gj]  (stride 25: conflict-free)
            {
                float* rp = &red[tid * 25];
#pragma unroll
                for (int i = 0; i < 4; ++i) {
                    float2 vi = unpack2(accI[i]);
                    float2 vo = unpack2(accO[i]);
                    float2 vu = unpack2(accU[i]);
                    rp[i * 6 + 0] = vi.x; rp[i * 6 + 1] = vi.y;
                    rp[i * 6 + 2] = vo.x; rp[i * 6 + 3] = vo.y;
                    rp[i * 6 + 4] = vu.x; rp[i * 6 + 5] = vu.y;
                }
            }
            __syncthreads();

            // Reduce 4 slices + gates (rows ty*2+jr, unit uA0+tx)
            const int cg = tx >> 1, jj = tx & 1;
            float memv[2], outv[2];
#pragma unroll
            for (int jr = 0; jr < 2; ++jr) {
                int r = ty * 2 + jr;
                int base = ((r >> 2) * 8 + cg) * 25 + (r & 3) * 6 + jj;
                float aI = red[base] + red[64 * 25 + base] +
                           red[128 * 25 + base] + red[192 * 25 + base];
                float aO = red[base + 2] + red[64 * 25 + base + 2] +
                           red[128 * 25 + base + 2] + red[192 * 25 + base + 2];
                float aU = red[base + 4] + red[64 * 25 + base + 4] +
                           red[128 * 25 + base + 4] + red[192 * 25 + base + 4];
                float fi = jr ? fi1 : fi0, fo = jr ? fo1 : fo0;
                float fu = jr ? fu1 : fu0, gc = jr ? gc1 : gc0;
                memv[jr] = sigm_(aI + fi) * tanh_(aU + fu) + gc;
                outv[jr] = sigm_(aO + fo) * tanh_(memv[jr]);
            }
            g_out[rowA0 * UU + u] = outv[0];
            g_mem[rowA0 * UU + u] = memv[0];
            g_out[rowA1 * UU + u] = outv[1];
            g_mem[rowA1 * UU + u] = memv[1];
        }
        gsync();

        // ================= Phase C: GEMM2 (k-split 4, FFMA2) + scatter =======
        {
            // Scatter-consumer prefetch (row bC0+ty, cols cC0+tx*2..+1)
            const int b  = bC0 + ty;
            const int cc = cC0 + tx * 2;
            int po = post[b * NN + t];
            int om = po >= 0;
            int tg = om ? po : 0;
            int pr = parents[b * NN + tg];
            int pm = om && (pr >= 0);
            int pa = pr < 0 ? 0 : pr;
            float2 fx    = *(const float2*)&g_fiou[((size_t)b * NN + pa) * 1024 + cc];
            float2 csh_o = *(const float2*)&g_csh[((size_t)b * NN + pa) * UU + cc];
            float2 gcs_o = *(const float2*)&g_gcs[((size_t)b * NN + pa) * UU + cc];
            float2 mm    = __ldcg((const float2*)&g_mem[b * UU + cc]);

            // Load out rows (16 x 256) into smem
#pragma unroll
            for (int j = 0; j < 4; ++j) {
                int f4 = tid + j * 256;
                int r = f4 >> 6, q = f4 & 63;
                float4 v = __ldcg((const float4*)&g_out[(bC0 + r) * UU + q * 4]);
                *(float4*)&outS[r * 260 + q * 4] = v;
            }
            __syncthreads();

            // k-slice accumulate: 2 rows x 2 col-pairs (FFMA2)
            ull accP[2][2] = {{0ull, 0ull}, {0ull, 0ull}};
            const float* o0 = &outS[(rgC * 2) * 260 + k0];
            const float* o1 = o0 + 260;
#pragma unroll 4
            for (int k = 0; k < 64; ++k) {
                const float* wp = &hfF[(k0 + k) * 36 + cgC * 4];
                ull w01 = *(const ull*)&wp[0];
                ull w23 = *(const ull*)&wp[2];
                float a0 = o0[k], a1 = o1[k];
                ull p0 = pack2(a0, a0), p1 = pack2(a1, a1);
                ffma2(accP[0][0], p0, w01); ffma2(accP[0][1], p0, w23);
                ffma2(accP[1][0], p1, w01); ffma2(accP[1][1], p1, w23);
            }
            {
                float* rp = &red[tid * 9];
#pragma unroll
                for (int i = 0; i < 2; ++i) {
                    float2 v01 = unpack2(accP[i][0]);
                    float2 v23 = unpack2(accP[i][1]);
                    rp[i * 4 + 0] = v01.x; rp[i * 4 + 1] = v01.y;
                    rp[i * 4 + 2] = v23.x; rp[i * 4 + 3] = v23.y;
                }
            }
            __syncthreads();

            // Reduce + gated scatter
            float accv[2];
#pragma unroll
            for (int j = 0; j < 2; ++j) {
                int cl = tx * 2 + j;
                int base = ((ty >> 1) * 8 + (cl >> 2)) * 9 + (ty & 1) * 4 + (cl & 3);
                accv[j] = red[base] + red[64 * 9 + base] +
                          red[128 * 9 + base] + red[192 * 9 + base];
            }
            float2 outp = *(const float2*)&outS[ty * 260 + cc];
            float gx = sigm_(accv[0] + fx.x) * mm.x;
            float gy = sigm_(accv[1] + fx.y) * mm.y;
            if (pm) {
                *(float2*)&g_csh[((size_t)b * NN + pa) * UU + cc] =
                    make_float2(csh_o.x + outp.x, csh_o.y + outp.y);
                *(float2*)&g_gcs[((size_t)b * NN + pa) * UU + cc] =
                    make_float2(gcs_o.x + gx, gcs_o.y + gy);
            }
            if (om) {
                *(float2*)&hs[((size_t)b * NN + tg) * UU + cc] = outp;
            }
        }
        gsync();
    }
}

// ---------------------------------------------------------------------------
// Launch: 3 graph nodes. Dynamic smem for k_recur is 162.0 KB.
// ---------------------------------------------------------------------------
extern "C" void kernel_launch(void* const* d_in, const int* in_sizes, int n_in,
                              void* d_out, int out_size)
{
    const float* inputs  = (const float*)d_in[0];
    const int*   parents = (const int*)  d_in[1];
    const int*   post    = (const int*)  d_in[2];
    const float* xf      = (const float*)d_in[3];
    const float* hfk     = (const float*)d_in[4];
    const float* hiou    = (const float*)d_in[5];
    const float* bias    = (const float*)d_in[6];
    float* hs = (float*)d_out;

    (void)in_sizes; (void)n_in; (void)out_size;

    static int smem_set = 0;
    const int SMEM_BYTES = 40512 * 4;
    if (!smem_set) {
        cudaFuncSetAttribute(k_recur, cudaFuncAttributeMaxDynamicSharedMemorySize,
                             SMEM_BYTES);
        smem_set = 1;
    }

    k_zero<<<2048, 256>>>((float4*)hs);
    k_precompute<<<dim3(8, 512), 256>>>(inputs, xf, bias);
    k_recur<<<128, 256, SMEM_BYTES>>>(parents, post, hfk, hiou, hs);
}

// round 12
// speedup vs baseline: 2.2681x; 1.0484x over previous
#include <cuda_runtime.h>
#include <math.h>

#define BB 256
#define NN 256
#define DD 256
#define UU 256

typedef unsigned long long ull;

// ---------------------------------------------------------------------------
// Packed fp32x2 helpers (kept from R10; neutral vs FFMA but not worse)
// ---------------------------------------------------------------------------
__device__ __forceinline__ void ffma2(ull& d, ull a, ull b) {
    asm("fma.rn.f32x2 %0, %1, %2, %0;" : "+l"(d) : "l"(a), "l"(b));
}
__device__ __forceinline__ ull pack2(float x, float y) {
    ull r;
    asm("mov.b64 %0, {%1, %2};"
        : "=l"(r) : "r"(__float_as_uint(x)), "r"(__float_as_uint(y)));
    return r;
}
__device__ __forceinline__ float2 unpack2(ull v) {
    unsigned lo, hi;
    asm("mov.b64 {%0, %1}, %2;" : "=r"(lo), "=r"(hi) : "l"(v));
    return make_float2(__uint_as_float(lo), __uint_as_float(hi));
}

// ---------------------------------------------------------------------------
// Scratch (static __device__ arrays; no allocations allowed)
// ---------------------------------------------------------------------------
__device__ float g_fiou[(size_t)BB * NN * 1024];  // [b][n][1024]: 0..255=f, 256..511=i, 512..767=o, 768..1023=u
__device__ float g_csh[(size_t)BB * NN * UU];     // child-sum of hidden
__device__ float g_gcs[(size_t)BB * NN * UU];     // gated child cell sum
__device__ float g_out[BB * UU];                  // out for current step (per group rows)
__device__ float g_mem[BB * UU];                  // mem for current step

// Per-group barrier state, padded to separate 128B lines.
__device__ unsigned g_cnt[16 * 32];
__device__ volatile unsigned g_genA[16 * 32];

// Fast transcendentals: __expf rel-err ~2^-21, far inside the 1e-3 budget.
__device__ __forceinline__ float sigm_(float x) {
    return __fdividef(1.f, 1.f + __expf(-x));
}
__device__ __forceinline__ float tanh_(float x) {
    x = fminf(fmaxf(x, -15.f), 15.f);
    float e = __expf(2.f * x);
    return __fdividef(e - 1.f, e + 1.f);
}

// Group-local sense-reversal barrier (8 CTAs per group, all co-resident).
__device__ __forceinline__ void gsync_g(int grp) {
    __syncthreads();
    if (threadIdx.x == 0) {
        const int gi = grp * 32;
        unsigned my = g_genA[gi];
        __threadfence();  // release: publish this CTA's global writes to L2
        if (atomicAdd(&g_cnt[gi], 1u) == 7u) {
            g_cnt[gi] = 0;
            __threadfence();
            g_genA[gi] = my + 1;
        } else {
            while (g_genA[gi] == my) { }
        }
        __threadfence();  // acquire
    }
    __syncthreads();
}

// ---------------------------------------------------------------------------
// Zero csh, gcs, hs (output is poisoned before every timed replay)
// ---------------------------------------------------------------------------
__global__ void k_zero(float4* __restrict__ hs4) {
    const size_t n4 = ((size_t)BB * NN * UU) / 4;
    float4 z = make_float4(0.f, 0.f, 0.f, 0.f);
    float4* c4 = (float4*)g_csh;
    float4* g4 = (float4*)g_gcs;
    for (size_t i = (size_t)blockIdx.x * blockDim.x + threadIdx.x; i < n4;
         i += (size_t)gridDim.x * blockDim.x) {
        c4[i] = z; g4[i] = z; hs4[i] = z;
    }
}

// ---------------------------------------------------------------------------
// Precompute: g_fiou = inputs @ x_fiou + bias  (R10 FFMA2 version, unchanged)
// ---------------------------------------------------------------------------
__global__ void __launch_bounds__(256, 2) k_precompute(
    const float* __restrict__ X, const float* __restrict__ W,
    const float* __restrict__ bias)
{
    __shared__ __align__(16) float As[16 * 132];
    __shared__ __align__(16) float Ws[16 * 132];
    const int tid = threadIdx.x;
    const int ty  = tid >> 4;
    const int tx  = tid & 15;
    const int m0  = blockIdx.y * 128;
    const int n0  = blockIdx.x * 128;

    ull acc[8][4];
#pragma unroll
    for (int i = 0; i < 8; ++i)
#pragma unroll
        for (int j = 0; j < 4; ++j) acc[i][j] = 0ull;

    for (int kc = 0; kc < DD; kc += 16) {
#pragma unroll
        for (int it = 0; it < 2; ++it) {
            int v = tid + it * 256;
            int r = v >> 2, q = v & 3;
            float4 a = *(const float4*)&X[(size_t)(m0 + r) * DD + kc + q * 4];
            As[(q * 4 + 0) * 132 + r] = a.x;
            As[(q * 4 + 1) * 132 + r] = a.y;
            As[(q * 4 + 2) * 132 + r] = a.z;
            As[(q * 4 + 3) * 132 + r] = a.w;
        }
#pragma unroll
        for (int it = 0; it < 2; ++it) {
            int idx = tid + it * 256;
            int kk = idx >> 5, c4 = idx & 31;
            *(float4*)&Ws[kk * 132 + c4 * 4] =
                *(const float4*)&W[(size_t)(kc + kk) * 1024 + n0 + c4 * 4];
        }
        __syncthreads();
#pragma unroll
        for (int k = 0; k < 16; ++k) {
            float4 a0 = *(const float4*)&As[k * 132 + ty * 4];
            float4 a1 = *(const float4*)&As[k * 132 + 64 + ty * 4];
            ull w00 = *(const ull*)&Ws[k * 132 + tx * 4];
            ull w01 = *(const ull*)&Ws[k * 132 + tx * 4 + 2];
            ull w10 = *(const ull*)&Ws[k * 132 + 64 + tx * 4];
            ull w11 = *(const ull*)&Ws[k * 132 + 64 + tx * 4 + 2];
            float ar[8] = {a0.x, a0.y, a0.z, a0.w, a1.x, a1.y, a1.z, a1.w};
#pragma unroll
            for (int i = 0; i < 8; ++i) {
                ull ap = pack2(ar[i], ar[i]);
                ffma2(acc[i][0], ap, w00);
                ffma2(acc[i][1], ap, w01);
                ffma2(acc[i][2], ap, w10);
                ffma2(acc[i][3], ap, w11);
            }
        }
        __syncthreads();
    }
    float4 bv0 = *(const float4*)&bias[n0 + tx * 4];
    float4 bv1 = *(const float4*)&bias[n0 + 64 + tx * 4];
#pragma unroll
    for (int i = 0; i < 8; ++i) {
        int row = m0 + ((i < 4) ? (ty * 4 + i) : (64 + ty * 4 + (i - 4)));
        float2 p0 = unpack2(acc[i][0]);
        float2 p1 = unpack2(acc[i][1]);
        float2 p2 = unpack2(acc[i][2]);
        float2 p3 = unpack2(acc[i][3]);
        float4 o0 = make_float4(p0.x + bv0.x, p0.y + bv0.y, p1.x + bv0.z, p1.y + bv0.w);
        float4 o1 = make_float4(p2.x + bv1.x, p2.y + bv1.y, p3.x + bv1.z, p3.y + bv1.w);
        *(float4*)&g_fiou[(size_t)row * 1024 + n0 + tx * 4] = o0;
        *(float4*)&g_fiou[(size_t)row * 1024 + n0 + 64 + tx * 4] = o1;
    }
}

// ---------------------------------------------------------------------------
// Persistent recurrence: 16 INDEPENDENT groups of 8 CTAs. Each group owns 16
// batch rows and runs its own 256-step scan with group-local barriers —
// no cross-group coupling, so stragglers don't stall the whole chip.
//
// Per group/step:
//  Phase A (8 CTAs): each CTA computes iou for 16 rows x 32 units (x3 gates),
//    full K=256 with intra-CTA K-split 4, then applies gates -> g_out/g_mem.
//  Phase C (8 CTAs): each CTA computes out@h_f for 16 rows x 32 cols
//    (K-split 4) + gated scatter into csh/gcs (unique owner per (b,col)).
//
// Dynamic smem (floats):
//   [0     ,24576) WsF : h_iou slice [256 k][96 = 3 gates x 32 units]
//   [24576 ,33792) hfF : h_f  slice [256 k][36]
//   [33792 ,38144) AsT : csh gather, k-major [256 k][17]
//   [38144 ,42304) outS: out rows [16][260]
//   [42304 ,48704) red : cross-slice partials (A: 256*25; C aliases 256*9)
// Total 190.3 KB.
// ---------------------------------------------------------------------------
__global__ void __launch_bounds__(256, 1) k_recur(
    const int*   __restrict__ parents,
    const int*   __restrict__ post,
    const float* __restrict__ hf,
    const float* __restrict__ hiou,
    float*       __restrict__ hs)
{
    extern __shared__ __align__(16) float sm[];
    float* WsF  = sm;              // [256][96]
    float* hfF  = sm + 24576;      // [256][36]
    float* AsT  = sm + 33792;      // [256][17]  k-major
    float* outS = sm + 38144;      // [16][260]
    float* red  = sm + 42304;      // A: [256][25]; C: [256][9]

    const int c    = blockIdx.x;
    const int grp  = c >> 3;       // 16 groups
    const int cig  = c & 7;        // CTA within group
    const int tid  = threadIdx.x;
    const int tx   = tid & 15;
    const int ty   = tid >> 4;

    const int bG0 = grp * 16;      // group's 16 batch rows
    const int uA0 = cig * 32;      // phase A: this CTA's 32 units
    const int cC0 = cig * 32;      // phase C: this CTA's 32 cols

    // K-split decomposition: slice sK (0..3), local lK (0..63)
    const int sK = tid >> 6;
    const int lK = tid & 63;
    const int rgA = lK >> 4;       // rows rgA*4 .. +3 (of 16)
    const int cgA = lK & 15;       // unit pair cgA*2, +1 (of 32)
    const int rgC = lK >> 3;       // rows rgC*2, +1 (of 16)
    const int cgC = lK & 7;        // cols cgC*4 .. +3 (of 32)
    const int k0  = sK * 64;

    // ---- One-time weight staging (resident across all 256 steps) ----
    for (int idx = tid; idx < 256 * 96; idx += 256) {
        int kk = idx / 96, rem = idx % 96;
        int gate = rem >> 5, ul = rem & 31;
        WsF[kk * 96 + gate * 32 + ul] =
            hiou[(size_t)kk * 768 + gate * 256 + uA0 + ul];
    }
    for (int idx = tid; idx < 256 * 32; idx += 256) {
        int kk = idx >> 5, cl = idx & 31;
        hfF[kk * 36 + cl] = hf[(size_t)kk * UU + cC0 + cl];
    }
    __syncthreads();

    for (int t = 0; t < NN; ++t) {
        // ================= Phase A: GEMM1 (k-split 4) + gates =================
        {
            // Gate-consumer prefetch: row bG0+ty, units uA0 + 2tx, 2tx+1
            const int bA = bG0 + ty;
            const int u2 = uA0 + tx * 2;
            int poA = post[bA * NN + t];
            int tgA = poA < 0 ? 0 : poA;
            size_t fb = ((size_t)bA * NN + tgA) * 1024 + u2;
            float2 fi = *(const float2*)&g_fiou[fb + 256];
            float2 fo = *(const float2*)&g_fiou[fb + 512];
            float2 fu = *(const float2*)&g_fiou[fb + 768];
            float2 gc = __ldcg((const float2*)&g_gcs[((size_t)bA * NN + tgA) * UU + u2]);

            // Gather csh rows -> AsT (k-major, stride 17)
            {
                int r = tid >> 4, q = tid & 15;   // 16 lanes per row
                int po = post[(bG0 + r) * NN + t];
                int tg = po < 0 ? 0 : po;
                const float4* src =
                    (const float4*)&g_csh[(((size_t)(bG0 + r)) * NN + tg) * UU];
#pragma unroll
                for (int j = 0; j < 4; ++j) {
                    float4 v = __ldcg(&src[q + j * 16]);
                    int ks = (q + j * 16) * 4;
                    AsT[(ks + 0) * 17 + r] = v.x;
                    AsT[(ks + 1) * 17 + r] = v.y;
                    AsT[(ks + 2) * 17 + r] = v.z;
                    AsT[(ks + 3) * 17 + r] = v.w;
                }
            }
            __syncthreads();

            // k-slice accumulate: 4 rows x 3 gate-pairs
            ull accI[4] = {0ull, 0ull, 0ull, 0ull};
            ull accO[4] = {0ull, 0ull, 0ull, 0ull};
            ull accU[4] = {0ull, 0ull, 0ull, 0ull};

#pragma unroll 4
            for (int k = 0; k < 64; ++k) {
                const int kk = k0 + k;
                const float* ap = &AsT[kk * 17 + rgA * 4];
                const float* wp = &WsF[kk * 96 + cgA * 2];
                ull wI = *(const ull*)&wp[0];
                ull wO = *(const ull*)&wp[32];
                ull wU = *(const ull*)&wp[64];
                float a0 = ap[0], a1 = ap[1], a2 = ap[2], a3 = ap[3];
                ull p0 = pack2(a0, a0), p1 = pack2(a1, a1);
                ull p2 = pack2(a2, a2), p3 = pack2(a3, a3);
                ffma2(accI[0], p0, wI); ffma2(accO[0], p0, wO); ffma2(accU[0], p0, wU);
                ffma2(accI[1], p1, wI); ffma2(accO[1], p1, wO); ffma2(accU[1], p1, wU);
                ffma2(accI[2], p2, wI); ffma2(accO[2], p2, wO); ffma2(accU[2], p2, wU);
                ffma2(accI[3], p3, wI); ffma2(accO[3], p3, wO); ffma2(accU[3], p3, wU);
            }
            // Partials -> red[tid*25 + i*6 + {0..5}]
            {
                float* rp = &red[tid * 25];
#pragma unroll
                for (int i = 0; i < 4; ++i) {
                    float2 vi = unpack2(accI[i]);
                    float2 vo = unpack2(accO[i]);
                    float2 vu = unpack2(accU[i]);
                    rp[i * 6 + 0] = vi.x; rp[i * 6 + 1] = vi.y;
                    rp[i * 6 + 2] = vo.x; rp[i * 6 + 3] = vo.y;
                    rp[i * 6 + 4] = vu.x; rp[i * 6 + 5] = vu.y;
                }
            }
            __syncthreads();

            // Reduce 4 slices + gates: row ty, units 2tx, 2tx+1
            // Producer: lK = (ty>>2)*16 + tx, i = ty&3
            const int baseL = ((ty >> 2) * 16 + tx) * 25 + (ty & 3) * 6;
            float memv[2], outv[2];
#pragma unroll
            for (int jj = 0; jj < 2; ++jj) {
                int base = baseL + jj;
                float aI = red[base] + red[1600 + base] +
                           red[3200 + base] + red[4800 + base];
                float aO = red[base + 2] + red[1600 + base + 2] +
                           red[3200 + base + 2] + red[4800 + base + 2];
                float aU = red[base + 4] + red[1600 + base + 4] +
                           red[3200 + base + 4] + red[4800 + base + 4];
                float fiv = jj ? fi.y : fi.x;
                float fov = jj ? fo.y : fo.x;
                float fuv = jj ? fu.y : fu.x;
                float gcv = jj ? gc.y : gc.x;
                memv[jj] = sigm_(aI + fiv) * tanh_(aU + fuv) + gcv;
                outv[jj] = sigm_(aO + fov) * tanh_(memv[jj]);
            }
            *(float2*)&g_out[bA * UU + u2] = make_float2(outv[0], outv[1]);
            *(float2*)&g_mem[bA * UU + u2] = make_float2(memv[0], memv[1]);
        }
        gsync_g(grp);

        // ================= Phase C: GEMM2 (k-split 4) + gated scatter =========
        {
            // Scatter-consumer prefetch: row bG0+ty, cols cC0 + 2tx, 2tx+1
            const int b  = bG0 + ty;
            const int cc = cC0 + tx * 2;
            int po = post[b * NN + t];
            int om = po >= 0;
            int tg = om ? po : 0;
            int pr = parents[b * NN + tg];
            int pm = om && (pr >= 0);
            int pa = pr < 0 ? 0 : pr;
            float2 fx    = *(const float2*)&g_fiou[((size_t)b * NN + pa) * 1024 + cc];
            float2 csh_o = *(const float2*)&g_csh[((size_t)b * NN + pa) * UU + cc];
            float2 gcs_o = *(const float2*)&g_gcs[((size_t)b * NN + pa) * UU + cc];
            float2 mm    = __ldcg((const float2*)&g_mem[b * UU + cc]);

            // Load group's out rows (16 x 256) into smem
#pragma unroll
            for (int j = 0; j < 4; ++j) {
                int f4 = tid + j * 256;
                int r = f4 >> 6, q = f4 & 63;
                float4 v = __ldcg((const float4*)&g_out[(bG0 + r) * UU + q * 4]);
                *(float4*)&outS[r * 260 + q * 4] = v;
            }
            __syncthreads();

            // k-slice accumulate: 2 rows x 2 col-pairs
            ull accP[2][2] = {{0ull, 0ull}, {0ull, 0ull}};
            const float* o0 = &outS[(rgC * 2) * 260 + k0];
            const float* o1 = o0 + 260;
#pragma unroll 4
            for (int k = 0; k < 64; ++k) {
                const float* wp = &hfF[(k0 + k) * 36 + cgC * 4];
                ull w01 = *(const ull*)&wp[0];
                ull w23 = *(const ull*)&wp[2];
                float a0 = o0[k], a1 = o1[k];
                ull p0 = pack2(a0, a0), p1 = pack2(a1, a1);
                ffma2(accP[0][0], p0, w01); ffma2(accP[0][1], p0, w23);
                ffma2(accP[1][0], p1, w01); ffma2(accP[1][1], p1, w23);
            }
            {
                float* rp = &red[tid * 9];
#pragma unroll
                for (int i = 0; i < 2; ++i) {
                    float2 v01 = unpack2(accP[i][0]);
                    float2 v23 = unpack2(accP[i][1]);
                    rp[i * 4 + 0] = v01.x; rp[i * 4 + 1] = v01.y;
                    rp[i * 4 + 2] = v23.x; rp[i * 4 + 3] = v23.y;
                }
            }
            __syncthreads();

            // Reduce + gated scatter
            float accv[2];
#pragma unroll
            for (int j = 0; j < 2; ++j) {
                int cl = tx * 2 + j;
                int base = ((ty >> 1) * 8 + (cl >> 2)) * 9 + (ty & 1) * 4 + (cl & 3);
                accv[j] = red[base] + red[576 + base] +
                          red[1152 + base] + red[1728 + base];
            }
            float2 outp = *(const float2*)&outS[ty * 260 + cc];
            float gx = sigm_(accv[0] + fx.x) * mm.x;
            float gy = sigm_(accv[1] + fx.y) * mm.y;
            if (pm) {
                *(float2*)&g_csh[((size_t)b * NN + pa) * UU + cc] =
                    make_float2(csh_o.x + outp.x, csh_o.y + outp.y);
                *(float2*)&g_gcs[((size_t)b * NN + pa) * UU + cc] =
                    make_float2(gcs_o.x + gx, gcs_o.y + gy);
            }
            if (om) {
                *(float2*)&hs[((size_t)b * NN + tg) * UU + cc] = outp;
            }
        }
        gsync_g(grp);
    }
}

// ---------------------------------------------------------------------------
// Launch: 3 graph nodes. Dynamic smem for k_recur is 190.3 KB.
// ---------------------------------------------------------------------------
extern "C" void kernel_launch(void* const* d_in, const int* in_sizes, int n_in,
                              void* d_out, int out_size)
{
    const float* inputs  = (const float*)d_in[0];
    const int*   parents = (const int*)  d_in[1];
    const int*   post    = (const int*)  d_in[2];
    const float* xf      = (const float*)d_in[3];
    const float* hfk     = (const float*)d_in[4];
    const float* hiou    = (const float*)d_in[5];
    const float* bias    = (const float*)d_in[6];
    float* hs = (float*)d_out;

    (void)in_sizes; (void)n_in; (void)out_size;

    static int smem_set = 0;
    const int SMEM_BYTES = 48704 * 4;
    if (!smem_set) {
        cudaFuncSetAttribute(k_recur, cudaFuncAttributeMaxDynamicSharedMemorySize,
                             SMEM_BYTES);
        smem_set = 1;
    }

    k_zero<<<2048, 256>>>((float4*)hs);
    k_precompute<<<dim3(8, 512), 256>>>(inputs, xf, bias);
    k_recur<<<128, 256, SMEM_BYTES>>>(parents, post, hfk, hiou, hs);
}

// round 14
// speedup vs baseline: 2.3888x; 1.0532x over previous
#include <cuda_runtime.h>
#include <cuda_bf16.h>
#include <math.h>
#include <stdint.h>

#define BB 256
#define NN 256
#define DD 256
#define UU 256

typedef unsigned long long ull;

// ---------------------------------------------------------------------------
// Packed fp32x2 helpers (used by k_recur)
// ---------------------------------------------------------------------------
__device__ __forceinline__ void ffma2(ull& d, ull a, ull b) {
    asm("fma.rn.f32x2 %0, %1, %2, %0;" : "+l"(d) : "l"(a), "l"(b));
}
__device__ __forceinline__ ull pack2(float x, float y) {
    ull r;
    asm("mov.b64 %0, {%1, %2};"
        : "=l"(r) : "r"(__float_as_uint(x)), "r"(__float_as_uint(y)));
    return r;
}
__device__ __forceinline__ float2 unpack2(ull v) {
    unsigned lo, hi;
    asm("mov.b64 {%0, %1}, %2;" : "=r"(lo), "=r"(hi) : "l"(v));
    return make_float2(__uint_as_float(lo), __uint_as_float(hi));
}

// ---------------------------------------------------------------------------
// Scratch (static __device__ arrays; no allocations allowed)
// ---------------------------------------------------------------------------
__device__ float g_fiou[(size_t)BB * NN * 1024];  // [b][n][1024]: 0..255=f, 256..511=i, 512..767=o, 768..1023=u
__device__ float g_csh[(size_t)BB * NN * UU];     // child-sum of hidden
__device__ float g_gcs[(size_t)BB * NN * UU];     // gated child cell sum
__device__ float g_out[BB * UU];                  // out for current step
__device__ float g_mem[BB * UU];                  // mem for current step

// Per-group barrier state, padded to separate 128B lines.
__device__ unsigned g_cnt[16 * 32];
__device__ volatile unsigned g_genA[16 * 32];

// Fast transcendentals: __expf rel-err ~2^-21, far inside the 1e-3 budget.
__device__ __forceinline__ float sigm_(float x) {
    return __fdividef(1.f, 1.f + __expf(-x));
}
__device__ __forceinline__ float tanh_(float x) {
    x = fminf(fmaxf(x, -15.f), 15.f);
    float e = __expf(2.f * x);
    return __fdividef(e - 1.f, e + 1.f);
}

// Group-local sense-reversal barrier (8 CTAs per group, all co-resident).
__device__ __forceinline__ void gsync_g(int grp) {
    __syncthreads();
    if (threadIdx.x == 0) {
        const int gi = grp * 32;
        unsigned my = g_genA[gi];
        __threadfence();  // release
        if (atomicAdd(&g_cnt[gi], 1u) == 7u) {
            g_cnt[gi] = 0;
            __threadfence();
            g_genA[gi] = my + 1;
        } else {
            while (g_genA[gi] == my) { }
        }
        __threadfence();  // acquire
    }
    __syncthreads();
}

// ---------------------------------------------------------------------------
// Zero csh, gcs, hs (output is poisoned before every timed replay)
// ---------------------------------------------------------------------------
__global__ void k_zero(float4* __restrict__ hs4) {
    const size_t n4 = ((size_t)BB * NN * UU) / 4;
    float4 z = make_float4(0.f, 0.f, 0.f, 0.f);
    float4* c4 = (float4*)g_csh;
    float4* g4 = (float4*)g_gcs;
    for (size_t i = (size_t)blockIdx.x * blockDim.x + threadIdx.x; i < n4;
         i += (size_t)gridDim.x * blockDim.x) {
        c4[i] = z; g4[i] = z; hs4[i] = z;
    }
}

// ===========================================================================
// Tensor-core precompute via warp-level mma.sync (bf16 split, fp32 accum):
// g_fiou = inputs @ x_fiou + bias,  C[65536 x 1024] = X[65536x256] @ W[256x1024]
// X = Xh + Xl, W = Wh + Wl (bf16 hi + bf16 residual);
// C = Xh*Wh + Xl*Wh + Xh*Wl  (Xl*Wl ~2^-18 rel, dropped).
// CTA: 128x128 tile, 8 warps (2x4), warp tile 64x32, K chunks of 64.
// ===========================================================================
__device__ __forceinline__ uint32_t smem_u32(const void* p) {
    uint32_t a;
    asm("{ .reg .u64 t; cvta.to.shared.u64 t, %1; cvt.u32.u64 %0, t; }"
        : "=r"(a) : "l"(p));
    return a;
}
// pack two fp32 -> bf16x2 (x -> low half, y -> high half)
__device__ __forceinline__ uint32_t bf2(float x, float y) {
    uint32_t r;
    asm("cvt.rn.bf16x2.f32 %0, %1, %2;" : "=r"(r) : "f"(y), "f"(x));
    return r;
}
__device__ __forceinline__ void ldm_x4(uint32_t (&r)[4], uint32_t addr) {
    asm volatile("ldmatrix.sync.aligned.m8n8.x4.shared.b16 {%0,%1,%2,%3}, [%4];"
        : "=r"(r[0]), "=r"(r[1]), "=r"(r[2]), "=r"(r[3]) : "r"(addr));
}
__device__ __forceinline__ void mma_bf16(float (&d)[4], const uint32_t (&a)[4],
                                         uint32_t b0, uint32_t b1) {
    asm volatile(
        "mma.sync.aligned.m16n8k16.row.col.f32.bf16.bf16.f32 "
        "{%0,%1,%2,%3}, {%4,%5,%6,%7}, {%8,%9}, {%0,%1,%2,%3};"
        : "+f"(d[0]), "+f"(d[1]), "+f"(d[2]), "+f"(d[3])
        : "r"(a[0]), "r"(a[1]), "r"(a[2]), "r"(a[3]), "r"(b0), "r"(b1));
}

// SMEM regions (byte offsets; row stride 80 bf16 = 160 B, 16B-aligned rows)
#define PC_AH 0
#define PC_AL 20480
#define PC_BH 40960
#define PC_BL 61440
#define PC_SMEM 81920

__global__ void __launch_bounds__(256, 1) k_precompute_mma(
    const float* __restrict__ X, const float* __restrict__ W,
    const float* __restrict__ bias)
{
    extern __shared__ __align__(16) char smc[];
    const uint32_t sb = smem_u32(smc);
    const int tid  = threadIdx.x;
    const int lane = tid & 31;
    const int w    = tid >> 5;
    const int wm   = w >> 2;        // 0..1 -> m offset wm*64
    const int wn   = w & 3;         // 0..3 -> n offset wn*32
    const int N0   = blockIdx.x * 128;
    const int M0   = blockIdx.y * 128;

    float acc[4][4][4];
#pragma unroll
    for (int mi = 0; mi < 4; ++mi)
#pragma unroll
        for (int ni = 0; ni < 4; ++ni)
#pragma unroll
            for (int q = 0; q < 4; ++q) acc[mi][ni][q] = 0.f;

    for (int kc = 0; kc < 256; kc += 64) {
        if (kc) __syncthreads();   // prior chunk's mma consumers done

        // ---- stage A: X[M0..+128][kc..+64] -> bf16 hi/lo, [row][k] stride 80
        for (int i = tid; i < 2048; i += 256) {
            int r = i >> 4, q = i & 15;
            float4 v = *(const float4*)&X[(size_t)(M0 + r) * DD + kc + q * 4];
            float hx = __bfloat162float(__float2bfloat16(v.x));
            float hy = __bfloat162float(__float2bfloat16(v.y));
            float hz = __bfloat162float(__float2bfloat16(v.z));
            float hw = __bfloat162float(__float2bfloat16(v.w));
            uint32_t off = (uint32_t)(r * 160 + q * 8);
            *(uint2*)(smc + PC_AH + off) =
                make_uint2(bf2(v.x, v.y), bf2(v.z, v.w));
            *(uint2*)(smc + PC_AL + off) =
                make_uint2(bf2(v.x - hx, v.y - hy), bf2(v.z - hz, v.w - hw));
        }
        // ---- stage B transposed: Bt[n][k] = W[kc+k][N0+n], stride 80
        for (int i = tid; i < 4096; i += 256) {
            int n = i & 127, kp = i >> 7;
            int k = kp * 2;
            float w0 = W[(size_t)(kc + k) * 1024 + N0 + n];
            float w1 = W[(size_t)(kc + k + 1) * 1024 + N0 + n];
            float h0 = __bfloat162float(__float2bfloat16(w0));
            float h1 = __bfloat162float(__float2bfloat16(w1));
            uint32_t off = (uint32_t)(n * 160 + k * 2);
            *(uint32_t*)(smc + PC_BH + off) = bf2(w0, w1);
            *(uint32_t*)(smc + PC_BL + off) = bf2(w0 - h0, w1 - h1);
        }
        __syncthreads();

        // ---- mma over 4 k16 steps
#pragma unroll
        for (int kk = 0; kk < 4; ++kk) {
            const uint32_t kb = (uint32_t)(kk * 32 + (lane >> 4) * 16);
            uint32_t ah[4][4], al[4][4];
#pragma unroll
            for (int mi = 0; mi < 4; ++mi) {
                uint32_t ro = (uint32_t)((wm * 64 + mi * 16 + (lane & 15)) * 160) + kb;
                ldm_x4(ah[mi], sb + PC_AH + ro);
                ldm_x4(al[mi], sb + PC_AL + ro);
            }
            uint32_t bh[2][4], bl[2][4];
#pragma unroll
            for (int nj = 0; nj < 2; ++nj) {
                uint32_t ro = (uint32_t)((wn * 32 + nj * 16 + (lane & 15)) * 160) + kb;
                ldm_x4(bh[nj], sb + PC_BH + ro);
                ldm_x4(bl[nj], sb + PC_BL + ro);
            }
#pragma unroll
            for (int mi = 0; mi < 4; ++mi)
#pragma unroll
                for (int ni = 0; ni < 4; ++ni) {
                    int nj = ni >> 1, sel = ni & 1;
                    uint32_t bh0 = bh[nj][sel], bh1 = bh[nj][sel + 2];
                    mma_bf16(acc[mi][ni], ah[mi], bh0, bh1);               // Xh*Wh
                    mma_bf16(acc[mi][ni], al[mi], bh0, bh1);               // Xl*Wh
                    mma_bf16(acc[mi][ni], ah[mi], bl[nj][sel], bl[nj][sel + 2]); // Xh*Wl
                }
        }
    }

    // ---- epilogue: bias + store fp32
    const int gr = lane >> 2, tg = lane & 3;
#pragma unroll
    for (int ni = 0; ni < 4; ++ni) {
        int col = N0 + wn * 32 + ni * 8 + tg * 2;
        float2 bv = *(const float2*)&bias[col];
#pragma unroll
        for (int mi = 0; mi < 4; ++mi) {
            int row = M0 + wm * 64 + mi * 16 + gr;
            *(float2*)&g_fiou[(size_t)row * 1024 + col] =
                make_float2(acc[mi][ni][0] + bv.x, acc[mi][ni][1] + bv.y);
            *(float2*)&g_fiou[(size_t)(row + 8) * 1024 + col] =
                make_float2(acc[mi][ni][2] + bv.x, acc[mi][ni][3] + bv.y);
        }
    }
}

// ---------------------------------------------------------------------------
// Persistent recurrence: identical to R12 (16 groups x 8 CTAs, group barriers)
// ---------------------------------------------------------------------------
__global__ void __launch_bounds__(256, 1) k_recur(
    const int*   __restrict__ parents,
    const int*   __restrict__ post,
    const float* __restrict__ hf,
    const float* __restrict__ hiou,
    float*       __restrict__ hs)
{
    extern __shared__ __align__(16) float sm[];
    float* WsF  = sm;              // [256][96]
    float* hfF  = sm + 24576;      // [256][36]
    float* AsT  = sm + 33792;      // [256][17]  k-major
    float* outS = sm + 38144;      // [16][260]
    float* red  = sm + 42304;      // A: [256][25]; C: [256][9]

    const int c    = blockIdx.x;
    const int grp  = c >> 3;
    const int cig  = c & 7;
    const int tid  = threadIdx.x;
    const int tx   = tid & 15;
    const int ty   = tid >> 4;

    const int bG0 = grp * 16;
    const int uA0 = cig * 32;
    const int cC0 = cig * 32;

    const int sK = tid >> 6;
    const int lK = tid & 63;
    const int rgA = lK >> 4;
    const int cgA = lK & 15;
    const int rgC = lK >> 3;
    const int cgC = lK & 7;
    const int k0  = sK * 64;

    for (int idx = tid; idx < 256 * 96; idx += 256) {
        int kk = idx / 96, rem = idx % 96;
        int gate = rem >> 5, ul = rem & 31;
        WsF[kk * 96 + gate * 32 + ul] =
            hiou[(size_t)kk * 768 + gate * 256 + uA0 + ul];
    }
    for (int idx = tid; idx < 256 * 32; idx += 256) {
        int kk = idx >> 5, cl = idx & 31;
        hfF[kk * 36 + cl] = hf[(size_t)kk * UU + cC0 + cl];
    }
    __syncthreads();

    for (int t = 0; t < NN; ++t) {
        // ======== Phase A ========
        {
            const int bA = bG0 + ty;
            const int u2 = uA0 + tx * 2;
            int poA = post[bA * NN + t];
            int tgA = poA < 0 ? 0 : poA;
            size_t fb = ((size_t)bA * NN + tgA) * 1024 + u2;
            float2 fi = *(const float2*)&g_fiou[fb + 256];
            float2 fo = *(const float2*)&g_fiou[fb + 512];
            float2 fu = *(const float2*)&g_fiou[fb + 768];
            float2 gc = __ldcg((const float2*)&g_gcs[((size_t)bA * NN + tgA) * UU + u2]);

            {
                int r = tid >> 4, q = tid & 15;
                int po = post[(bG0 + r) * NN + t];
                int tg = po < 0 ? 0 : po;
                const float4* src =
                    (const float4*)&g_csh[(((size_t)(bG0 + r)) * NN + tg) * UU];
#pragma unroll
                for (int j = 0; j < 4; ++j) {
                    float4 v = __ldcg(&src[q + j * 16]);
                    int ks = (q + j * 16) * 4;
                    AsT[(ks + 0) * 17 + r] = v.x;
                    AsT[(ks + 1) * 17 + r] = v.y;
                    AsT[(ks + 2) * 17 + r] = v.z;
                    AsT[(ks + 3) * 17 + r] = v.w;
                }
            }
            __syncthreads();

            ull accI[4] = {0ull, 0ull, 0ull, 0ull};
            ull accO[4] = {0ull, 0ull, 0ull, 0ull};
            ull accU[4] = {0ull, 0ull, 0ull, 0ull};

#pragma unroll 4
            for (int k = 0; k < 64; ++k) {
                const int kk = k0 + k;
                const float* ap = &AsT[kk * 17 + rgA * 4];
                const float* wp = &WsF[kk * 96 + cgA * 2];
                ull wI = *(const ull*)&wp[0];
                ull wO = *(const ull*)&wp[32];
                ull wU = *(const ull*)&wp[64];
                float a0 = ap[0], a1 = ap[1], a2 = ap[2], a3 = ap[3];
                ull p0 = pack2(a0, a0), p1 = pack2(a1, a1);
                ull p2 = pack2(a2, a2), p3 = pack2(a3, a3);
                ffma2(accI[0], p0, wI); ffma2(accO[0], p0, wO); ffma2(accU[0], p0, wU);
                ffma2(accI[1], p1, wI); ffma2(accO[1], p1, wO); ffma2(accU[1], p1, wU);
                ffma2(accI[2], p2, wI); ffma2(accO[2], p2, wO); ffma2(accU[2], p2, wU);
                ffma2(accI[3], p3, wI); ffma2(accO[3], p3, wO); ffma2(accU[3], p3, wU);
            }
            {
                float* rp = &red[tid * 25];
#pragma unroll
                for (int i = 0; i < 4; ++i) {
                    float2 vi = unpack2(accI[i]);
                    float2 vo = unpack2(accO[i]);
                    float2 vu = unpack2(accU[i]);
                    rp[i * 6 + 0] = vi.x; rp[i * 6 + 1] = vi.y;
                    rp[i * 6 + 2] = vo.x; rp[i * 6 + 3] = vo.y;
                    rp[i * 6 + 4] = vu.x; rp[i * 6 + 5] = vu.y;
                }
            }
            __syncthreads();

            const int baseL = ((ty >> 2) * 16 + tx) * 25 + (ty & 3) * 6;
            float memv[2], outv[2];
#pragma unroll
            for (int jj = 0; jj < 2; ++jj) {
                int base = baseL + jj;
                float aI = red[base] + red[1600 + base] +
                           red[3200 + base] + red[4800 + base];
                float aO = red[base + 2] + red[1600 + base + 2] +
                           red[3200 + base + 2] + red[4800 + base + 2];
                float aU = red[base + 4] + red[1600 + base + 4] +
                           red[3200 + base + 4] + red[4800 + base + 4];
                float fiv = jj ? fi.y : fi.x;
                float fov = jj ? fo.y : fo.x;
                float fuv = jj ? fu.y : fu.x;
                float gcv = jj ? gc.y : gc.x;
                memv[jj] = sigm_(aI + fiv) * tanh_(aU + fuv) + gcv;
                outv[jj] = sigm_(aO + fov) * tanh_(memv[jj]);
            }
            *(float2*)&g_out[bA * UU + u2] = make_float2(outv[0], outv[1]);
            *(float2*)&g_mem[bA * UU + u2] = make_float2(memv[0], memv[1]);
        }
        gsync_g(grp);

        // ======== Phase C ========
        {
            const int b  = bG0 + ty;
            const int cc = cC0 + tx * 2;
            int po = post[b * NN + t];
            int om = po >= 0;
            int tg = om ? po : 0;
            int pr = parents[b * NN + tg];
            int pm = om && (pr >= 0);
            int pa = pr < 0 ? 0 : pr;
            float2 fx    = *(const float2*)&g_fiou[((size_t)b * NN + pa) * 1024 + cc];
            float2 csh_o = *(const float2*)&g_csh[((size_t)b * NN + pa) * UU + cc];
            float2 gcs_o = *(const float2*)&g_gcs[((size_t)b * NN + pa) * UU + cc];
            float2 mm    = __ldcg((const float2*)&g_mem[b * UU + cc]);

#pragma unroll
            for (int j = 0; j < 4; ++j) {
                int f4 = tid + j * 256;
                int r = f4 >> 6, q = f4 & 63;
                float4 v = __ldcg((const float4*)&g_out[(bG0 + r) * UU + q * 4]);
                *(float4*)&outS[r * 260 + q * 4] = v;
            }
            __syncthreads();

            ull accP[2][2] = {{0ull, 0ull}, {0ull, 0ull}};
            const float* o0 = &outS[(rgC * 2) * 260 + k0];
            const float* o1 = o0 + 260;
#pragma unroll 4
            for (int k = 0; k < 64; ++k) {
                const float* wp = &hfF[(k0 + k) * 36 + cgC * 4];
                ull w01 = *(const ull*)&wp[0];
                ull w23 = *(const ull*)&wp[2];
                float a0 = o0[k], a1 = o1[k];
                ull p0 = pack2(a0, a0), p1 = pack2(a1, a1);
                ffma2(accP[0][0], p0, w01); ffma2(accP[0][1], p0, w23);
                ffma2(accP[1][0], p1, w01); ffma2(accP[1][1], p1, w23);
            }
            {
                float* rp = &red[tid * 9];
#pragma unroll
                for (int i = 0; i < 2; ++i) {
                    float2 v01 = unpack2(accP[i][0]);
                    float2 v23 = unpack2(accP[i][1]);
                    rp[i * 4 + 0] = v01.x; rp[i * 4 + 1] = v01.y;
                    rp[i * 4 + 2] = v23.x; rp[i * 4 + 3] = v23.y;
                }
            }
            __syncthreads();

            float accv[2];
#pragma unroll
            for (int j = 0; j < 2; ++j) {
                int cl = tx * 2 + j;
                int base = ((ty >> 1) * 8 + (cl >> 2)) * 9 + (ty & 1) * 4 + (cl & 3);
                accv[j] = red[base] + red[576 + base] +
                          red[1152 + base] + red[1728 + base];
            }
            float2 outp = *(const float2*)&outS[ty * 260 + cc];
            float gx = sigm_(accv[0] + fx.x) * mm.x;
            float gy = sigm_(accv[1] + fx.y) * mm.y;
            if (pm) {
                *(float2*)&g_csh[((size_t)b * NN + pa) * UU + cc] =
                    make_float2(csh_o.x + outp.x, csh_o.y + outp.y);
                *(float2*)&g_gcs[((size_t)b * NN + pa) * UU + cc] =
                    make_float2(gcs_o.x + gx, gcs_o.y + gy);
            }
            if (om) {
                *(float2*)&hs[((size_t)b * NN + tg) * UU + cc] = outp;
            }
        }
        gsync_g(grp);
    }
}

// ---------------------------------------------------------------------------
// Launch: 3 graph nodes.
// ---------------------------------------------------------------------------
extern "C" void kernel_launch(void* const* d_in, const int* in_sizes, int n_in,
                              void* d_out, int out_size)
{
    const float* inputs  = (const float*)d_in[0];
    const int*   parents = (const int*)  d_in[1];
    const int*   post    = (const int*)  d_in[2];
    const float* xf      = (const float*)d_in[3];
    const float* hfk     = (const float*)d_in[4];
    const float* hiou    = (const float*)d_in[5];
    const float* bias    = (const float*)d_in[6];
    float* hs = (float*)d_out;

    (void)in_sizes; (void)n_in; (void)out_size;

    static int smem_set = 0;
    const int SMEM_RECUR = 48704 * 4;
    if (!smem_set) {
        cudaFuncSetAttribute(k_recur, cudaFuncAttributeMaxDynamicSharedMemorySize,
                             SMEM_RECUR);
        cudaFuncSetAttribute(k_precompute_mma,
                             cudaFuncAttributeMaxDynamicSharedMemorySize, PC_SMEM);
        smem_set = 1;
    }

    k_zero<<<2048, 256>>>((float4*)hs);
    k_precompute_mma<<<dim3(8, 512), 256, PC_SMEM>>>(inputs, xf, bias);
    k_recur<<<128, 256, SMEM_RECUR>>>(parents, post, hfk, hiou, hs);
}

// round 15
// speedup vs baseline: 2.9826x; 1.2486x over previous
#include <cuda_runtime.h>
#include <cuda_bf16.h>
#include <math.h>
#include <stdint.h>

#define BB 256
#define NN 256
#define DD 256
#define UU 256

typedef unsigned long long ull;

// ---------------------------------------------------------------------------
// Scratch (static __device__ arrays; no allocations allowed)
// ---------------------------------------------------------------------------
__device__ float g_fiou[(size_t)BB * NN * 1024];  // [b][n][1024]: 0..255=f, 256..511=i, 512..767=o, 768..1023=u
__device__ float g_csh[(size_t)BB * NN * UU];     // child-sum of hidden
__device__ float g_gcs[(size_t)BB * NN * UU];     // gated child cell sum
__device__ float g_out[BB * UU];                  // out for current step
__device__ float g_mem[BB * UU];                  // mem for current step

// Per-group barrier state, padded to separate 128B lines.
__device__ unsigned g_cnt[16 * 32];
__device__ volatile unsigned g_genA[16 * 32];

// Fast transcendentals: __expf rel-err ~2^-21, far inside the 1e-3 budget.
__device__ __forceinline__ float sigm_(float x) {
    return __fdividef(1.f, 1.f + __expf(-x));
}
__device__ __forceinline__ float tanh_(float x) {
    x = fminf(fmaxf(x, -15.f), 15.f);
    float e = __expf(2.f * x);
    return __fdividef(e - 1.f, e + 1.f);
}

// Group-local sense-reversal barrier (8 CTAs per group, all co-resident).
__device__ __forceinline__ void gsync_g(int grp) {
    __syncthreads();
    if (threadIdx.x == 0) {
        const int gi = grp * 32;
        unsigned my = g_genA[gi];
        __threadfence();  // release
        if (atomicAdd(&g_cnt[gi], 1u) == 7u) {
            g_cnt[gi] = 0;
            __threadfence();
            g_genA[gi] = my + 1;
        } else {
            while (g_genA[gi] == my) { }
        }
        __threadfence();  // acquire
    }
    __syncthreads();
}

// ---------------------------------------------------------------------------
// Zero csh, gcs, hs (output is poisoned before every timed replay)
// ---------------------------------------------------------------------------
__global__ void k_zero(float4* __restrict__ hs4) {
    const size_t n4 = ((size_t)BB * NN * UU) / 4;
    float4 z = make_float4(0.f, 0.f, 0.f, 0.f);
    float4* c4 = (float4*)g_csh;
    float4* g4 = (float4*)g_gcs;
    for (size_t i = (size_t)blockIdx.x * blockDim.x + threadIdx.x; i < n4;
         i += (size_t)gridDim.x * blockDim.x) {
        c4[i] = z; g4[i] = z; hs4[i] = z;
    }
}

// ---------------------------------------------------------------------------
// mma.sync helpers (layout recipe validated by R13's passing precompute)
// ---------------------------------------------------------------------------
__device__ __forceinline__ uint32_t smem_u32(const void* p) {
    uint32_t a;
    asm("{ .reg .u64 t; cvta.to.shared.u64 t, %1; cvt.u32.u64 %0, t; }"
        : "=r"(a) : "l"(p));
    return a;
}
// pack two fp32 -> bf16x2 (x -> low half, y -> high half)
__device__ __forceinline__ uint32_t bf2(float x, float y) {
    uint32_t r;
    asm("cvt.rn.bf16x2.f32 %0, %1, %2;" : "=r"(r) : "f"(y), "f"(x));
    return r;
}
__device__ __forceinline__ void ldm_x4(uint32_t (&r)[4], uint32_t addr) {
    asm volatile("ldmatrix.sync.aligned.m8n8.x4.shared.b16 {%0,%1,%2,%3}, [%4];"
        : "=r"(r[0]), "=r"(r[1]), "=r"(r[2]), "=r"(r[3]) : "r"(addr));
}
__device__ __forceinline__ void mma_bf16(float (&d)[4], const uint32_t (&a)[4],
                                         uint32_t b0, uint32_t b1) {
    asm volatile(
        "mma.sync.aligned.m16n8k16.row.col.f32.bf16.bf16.f32 "
        "{%0,%1,%2,%3}, {%4,%5,%6,%7}, {%8,%9}, {%0,%1,%2,%3};"
        : "+f"(d[0]), "+f"(d[1]), "+f"(d[2]), "+f"(d[3])
        : "r"(a[0]), "r"(a[1]), "r"(a[2]), "r"(a[3]), "r"(b0), "r"(b1));
}

// ===========================================================================
// Tensor-core precompute (unchanged from R13, passing)
// ===========================================================================
#define PC_AH 0
#define PC_AL 20480
#define PC_BH 40960
#define PC_BL 61440
#define PC_SMEM 81920

__global__ void __launch_bounds__(256, 1) k_precompute_mma(
    const float* __restrict__ X, const float* __restrict__ W,
    const float* __restrict__ bias)
{
    extern __shared__ __align__(16) char smc[];
    const uint32_t sb = smem_u32(smc);
    const int tid  = threadIdx.x;
    const int lane = tid & 31;
    const int w    = tid >> 5;
    const int wm   = w >> 2;
    const int wn   = w & 3;
    const int N0   = blockIdx.x * 128;
    const int M0   = blockIdx.y * 128;

    float acc[4][4][4];
#pragma unroll
    for (int mi = 0; mi < 4; ++mi)
#pragma unroll
        for (int ni = 0; ni < 4; ++ni)
#pragma unroll
            for (int q = 0; q < 4; ++q) acc[mi][ni][q] = 0.f;

    for (int kc = 0; kc < 256; kc += 64) {
        if (kc) __syncthreads();

        for (int i = tid; i < 2048; i += 256) {
            int r = i >> 4, q = i & 15;
            float4 v = *(const float4*)&X[(size_t)(M0 + r) * DD + kc + q * 4];
            float hx = __bfloat162float(__float2bfloat16(v.x));
            float hy = __bfloat162float(__float2bfloat16(v.y));
            float hz = __bfloat162float(__float2bfloat16(v.z));
            float hw = __bfloat162float(__float2bfloat16(v.w));
            uint32_t off = (uint32_t)(r * 160 + q * 8);
            *(uint2*)(smc + PC_AH + off) =
                make_uint2(bf2(v.x, v.y), bf2(v.z, v.w));
            *(uint2*)(smc + PC_AL + off) =
                make_uint2(bf2(v.x - hx, v.y - hy), bf2(v.z - hz, v.w - hw));
        }
        for (int i = tid; i < 4096; i += 256) {
            int n = i & 127, kp = i >> 7;
            int k = kp * 2;
            float w0 = W[(size_t)(kc + k) * 1024 + N0 + n];
            float w1 = W[(size_t)(kc + k + 1) * 1024 + N0 + n];
            float h0 = __bfloat162float(__float2bfloat16(w0));
            float h1 = __bfloat162float(__float2bfloat16(w1));
            uint32_t off = (uint32_t)(n * 160 + k * 2);
            *(uint32_t*)(smc + PC_BH + off) = bf2(w0, w1);
            *(uint32_t*)(smc + PC_BL + off) = bf2(w0 - h0, w1 - h1);
        }
        __syncthreads();

#pragma unroll
        for (int kk = 0; kk < 4; ++kk) {
            const uint32_t kb = (uint32_t)(kk * 32 + (lane >> 4) * 16);
            uint32_t ah[4][4], al[4][4];
#pragma unroll
            for (int mi = 0; mi < 4; ++mi) {
                uint32_t ro = (uint32_t)((wm * 64 + mi * 16 + (lane & 15)) * 160) + kb;
                ldm_x4(ah[mi], sb + PC_AH + ro);
                ldm_x4(al[mi], sb + PC_AL + ro);
            }
            uint32_t bh[2][4], bl[2][4];
#pragma unroll
            for (int nj = 0; nj < 2; ++nj) {
                uint32_t ro = (uint32_t)((wn * 32 + nj * 16 + (lane & 15)) * 160) + kb;
                ldm_x4(bh[nj], sb + PC_BH + ro);
                ldm_x4(bl[nj], sb + PC_BL + ro);
            }
#pragma unroll
            for (int mi = 0; mi < 4; ++mi)
#pragma unroll
                for (int ni = 0; ni < 4; ++ni) {
                    int nj = ni >> 1, sel = ni & 1;
                    uint32_t bh0 = bh[nj][sel], bh1 = bh[nj][sel + 2];
                    mma_bf16(acc[mi][ni], ah[mi], bh0, bh1);
                    mma_bf16(acc[mi][ni], al[mi], bh0, bh1);
                    mma_bf16(acc[mi][ni], ah[mi], bl[nj][sel], bl[nj][sel + 2]);
                }
        }
    }

    const int gr = lane >> 2, tg = lane & 3;
#pragma unroll
    for (int ni = 0; ni < 4; ++ni) {
        int col = N0 + wn * 32 + ni * 8 + tg * 2;
        float2 bv = *(const float2*)&bias[col];
#pragma unroll
        for (int mi = 0; mi < 4; ++mi) {
            int row = M0 + wm * 64 + mi * 16 + gr;
            *(float2*)&g_fiou[(size_t)row * 1024 + col] =
                make_float2(acc[mi][ni][0] + bv.x, acc[mi][ni][1] + bv.y);
            *(float2*)&g_fiou[(size_t)(row + 8) * 1024 + col] =
                make_float2(acc[mi][ni][2] + bv.x, acc[mi][ni][3] + bv.y);
        }
    }
}

// ===========================================================================
// Persistent recurrence with mma.sync GEMMs.
// 16 groups x 8 CTAs; per CTA: phase A tile 16 rows x (3 gates x 32 units),
// phase C tile 16 rows x 32 cols. Split-bf16 (hi+lo) on weights AND
// activations; 3 products share fp32 accumulators.
//
// SMEM byte layout (stride 528 B = 264 bf16 rows -> conflict-free ldmatrix):
//   WtH 0       (50688)  h_iou slice transposed [96 col][256 k] bf16 hi
//   WtL 50688   (50688)  ... lo
//   HfH 101376  (16896)  h_f slice transposed [32 col][256 k] hi
//   HfL 118272  (16896)
//   AsH 135168  (8448)   csh gather [16 row][256 k] hi
//   AsL 143616  (8448)
//   OuH 152064  (8448)   out [16 row][256 k] hi
//   OuL 160512  (8448)
//   OuF 168960  (16640)  out fp32 [16][260]
//   RED 185600  (25600)  cross-warp partials (A: [64][100]; C: [128][36])
// Total 211200 B.
// ===========================================================================
#define RC_WtH 0
#define RC_WtL 50688
#define RC_HfH 101376
#define RC_HfL 118272
#define RC_AsH 135168
#define RC_AsL 143616
#define RC_OuH 152064
#define RC_OuL 160512
#define RC_OuF 168960
#define RC_RED 185600
#define RC_SMEM 211200

__global__ void __launch_bounds__(256, 1) k_recur(
    const int*   __restrict__ parents,
    const int*   __restrict__ post,
    const float* __restrict__ hf,
    const float* __restrict__ hiou,
    float*       __restrict__ hs)
{
    extern __shared__ __align__(16) char smc[];
    const uint32_t sb = smem_u32(smc);
    float* red = (float*)(smc + RC_RED);

    const int c    = blockIdx.x;
    const int grp  = c >> 3;
    const int cig  = c & 7;
    const int tid  = threadIdx.x;
    const int lane = tid & 31;
    const int w    = tid >> 5;
    const int tx   = tid & 15;
    const int ty   = tid >> 4;

    const int bG0 = grp * 16;
    const int uA0 = cig * 32;
    const int cC0 = cig * 32;

    // ---- one-time weight staging: transposed, bf16 hi/lo ----
    for (int e = tid; e < 24576; e += 256) {
        int col = e % 96, k = e / 96;
        int gate = col >> 5, unit = col & 31;
        float v = hiou[(size_t)k * 768 + gate * 256 + uA0 + unit];
        __nv_bfloat16 h = __float2bfloat16(v);
        *(__nv_bfloat16*)(smc + RC_WtH + col * 528 + k * 2) = h;
        *(__nv_bfloat16*)(smc + RC_WtL + col * 528 + k * 2) =
            __float2bfloat16(v - __bfloat162float(h));
    }
    for (int e = tid; e < 8192; e += 256) {
        int col = e & 31, k = e >> 5;
        float v = hf[(size_t)k * 256 + cC0 + col];
        __nv_bfloat16 h = __float2bfloat16(v);
        *(__nv_bfloat16*)(smc + RC_HfH + col * 528 + k * 2) = h;
        *(__nv_bfloat16*)(smc + RC_HfL + col * 528 + k * 2) =
            __float2bfloat16(v - __bfloat162float(h));
    }
    __syncthreads();

    const int gr  = lane >> 2;
    const int tg2 = (lane & 3) * 2;

    for (int t = 0; t < NN; ++t) {
        // ================= Phase A: GEMM1 (mma) + gates =================
        {
            // Gate-consumer prefetch: row bG0+ty, units uA0 + 2tx, 2tx+1
            const int bA = bG0 + ty;
            const int u2 = uA0 + tx * 2;
            int poA = post[bA * NN + t];
            int tgA = poA < 0 ? 0 : poA;
            size_t fb = ((size_t)bA * NN + tgA) * 1024 + u2;
            float2 fi = *(const float2*)&g_fiou[fb + 256];
            float2 fo = *(const float2*)&g_fiou[fb + 512];
            float2 fu = *(const float2*)&g_fiou[fb + 768];
            float2 gc = __ldcg((const float2*)&g_gcs[((size_t)bA * NN + tgA) * UU + u2]);

            // Gather csh rows + convert to bf16 hi/lo
            {
                int r = tid >> 4, q0 = tid & 15;
                int po = post[(bG0 + r) * NN + t];
                int tg = po < 0 ? 0 : po;
                const float4* src =
                    (const float4*)&g_csh[(((size_t)(bG0 + r)) * NN + tg) * UU];
#pragma unroll
                for (int j = 0; j < 4; ++j) {
                    float4 v = __ldcg(&src[q0 + j * 16]);
                    float hx = __bfloat162float(__float2bfloat16(v.x));
                    float hy = __bfloat162float(__float2bfloat16(v.y));
                    float hz = __bfloat162float(__float2bfloat16(v.z));
                    float hw = __bfloat162float(__float2bfloat16(v.w));
                    uint32_t off = (uint32_t)(r * 528 + (q0 + j * 16) * 8);
                    *(uint2*)(smc + RC_AsH + off) =
                        make_uint2(bf2(v.x, v.y), bf2(v.z, v.w));
                    *(uint2*)(smc + RC_AsL + off) =
                        make_uint2(bf2(v.x - hx, v.y - hy), bf2(v.z - hz, v.w - hw));
                }
            }
            __syncthreads();

            // mma: warp w -> K-slice (w&3)*64, col half (w>>2)*48
            const int ks = w & 3;
            const int ch = w >> 2;
            float acc[6][4];
#pragma unroll
            for (int nt = 0; nt < 6; ++nt)
#pragma unroll
                for (int q = 0; q < 4; ++q) acc[nt][q] = 0.f;

#pragma unroll
            for (int kk = 0; kk < 4; ++kk) {
                const uint32_t kb = (uint32_t)((ks * 64 + kk * 16) * 2 + (lane >> 4) * 16);
                uint32_t ah[4], al[4];
                uint32_t aaddr = sb + RC_AsH + (uint32_t)((lane & 15) * 528) + kb;
                ldm_x4(ah, aaddr);
                ldm_x4(al, aaddr + (RC_AsL - RC_AsH));
#pragma unroll
                for (int nb = 0; nb < 3; ++nb) {
                    uint32_t baddr = sb + RC_WtH +
                        (uint32_t)((ch * 48 + nb * 16 + (lane & 15)) * 528) + kb;
                    uint32_t bh[4], bl[4];
                    ldm_x4(bh, baddr);
                    ldm_x4(bl, baddr + (RC_WtL - RC_WtH));
#pragma unroll
                    for (int sel = 0; sel < 2; ++sel) {
                        int nt = nb * 2 + sel;
                        mma_bf16(acc[nt], ah, bh[sel], bh[sel + 2]);
                        mma_bf16(acc[nt], al, bh[sel], bh[sel + 2]);
                        mma_bf16(acc[nt], ah, bl[sel], bl[sel + 2]);
                    }
                }
            }
            // partials -> red[ks*16 + row][col], stride 100
#pragma unroll
            for (int nt = 0; nt < 6; ++nt) {
                int col = ch * 48 + nt * 8 + tg2;
                *(float2*)&red[(ks * 16 + gr) * 100 + col] =
                    make_float2(acc[nt][0], acc[nt][1]);
                *(float2*)&red[(ks * 16 + gr + 8) * 100 + col] =
                    make_float2(acc[nt][2], acc[nt][3]);
            }
            __syncthreads();

            // reduce 4 slices + gates
            float memv[2], outv[2];
#pragma unroll
            for (int j = 0; j < 2; ++j) {
                int u = tx * 2 + j;
                float aI = 0.f, aO = 0.f, aU = 0.f;
#pragma unroll
                for (int s = 0; s < 4; ++s) {
                    int rb = (s * 16 + ty) * 100;
                    aI += red[rb + u];
                    aO += red[rb + 32 + u];
                    aU += red[rb + 64 + u];
                }
                float fiv = j ? fi.y : fi.x;
                float fov = j ? fo.y : fo.x;
                float fuv = j ? fu.y : fu.x;
                float gcv = j ? gc.y : gc.x;
                memv[j] = sigm_(aI + fiv) * tanh_(aU + fuv) + gcv;
                outv[j] = sigm_(aO + fov) * tanh_(memv[j]);
            }
            *(float2*)&g_out[bA * UU + u2] = make_float2(outv[0], outv[1]);
            *(float2*)&g_mem[bA * UU + u2] = make_float2(memv[0], memv[1]);
        }
        gsync_g(grp);

        // ================= Phase C: GEMM2 (mma) + gated scatter =================
        {
            // Scatter-consumer prefetch
            const int b  = bG0 + ty;
            const int cc = cC0 + tx * 2;
            int po = post[b * NN + t];
            int om = po >= 0;
            int tg = om ? po : 0;
            int pr = parents[b * NN + tg];
            int pm = om && (pr >= 0);
            int pa = pr < 0 ? 0 : pr;
            float2 fx    = *(const float2*)&g_fiou[((size_t)b * NN + pa) * 1024 + cc];
            float2 csh_o = *(const float2*)&g_csh[((size_t)b * NN + pa) * UU + cc];
            float2 gcs_o = *(const float2*)&g_gcs[((size_t)b * NN + pa) * UU + cc];
            float2 mm    = __ldcg((const float2*)&g_mem[b * UU + cc]);

            // Stage out rows: fp32 copy + bf16 hi/lo
            {
                int r = tid >> 4, q0 = tid & 15;
                const float4* src = (const float4*)&g_out[(bG0 + r) * UU];
#pragma unroll
                for (int j = 0; j < 4; ++j) {
                    float4 v = __ldcg(&src[q0 + j * 16]);
                    int q = q0 + j * 16;
                    *(float4*)(smc + RC_OuF + r * 1040 + q * 16) = v;
                    float hx = __bfloat162float(__float2bfloat16(v.x));
                    float hy = __bfloat162float(__float2bfloat16(v.y));
                    float hz = __bfloat162float(__float2bfloat16(v.z));
                    float hw = __bfloat162float(__float2bfloat16(v.w));
                    uint32_t off = (uint32_t)(r * 528 + q * 8);
                    *(uint2*)(smc + RC_OuH + off) =
                        make_uint2(bf2(v.x, v.y), bf2(v.z, v.w));
                    *(uint2*)(smc + RC_OuL + off) =
                        make_uint2(bf2(v.x - hx, v.y - hy), bf2(v.z - hz, v.w - hw));
                }
            }
            __syncthreads();

            // mma: warp w -> K-slice w*32 (2 k16 steps), 4 n8 tiles (32 cols)
            float accC[4][4];
#pragma unroll
            for (int nt = 0; nt < 4; ++nt)
#pragma unroll
                for (int q = 0; q < 4; ++q) accC[nt][q] = 0.f;

#pragma unroll
            for (int kk = 0; kk < 2; ++kk) {
                const uint32_t kb = (uint32_t)((w * 32 + kk * 16) * 2 + (lane >> 4) * 16);
                uint32_t ah[4], al[4];
                uint32_t aaddr = sb + RC_OuH + (uint32_t)((lane & 15) * 528) + kb;
                ldm_x4(ah, aaddr);
                ldm_x4(al, aaddr + (RC_OuL - RC_OuH));
#pragma unroll
                for (int nb = 0; nb < 2; ++nb) {
                    uint32_t baddr = sb + RC_HfH +
                        (uint32_t)((nb * 16 + (lane & 15)) * 528) + kb;
                    uint32_t bh[4], bl[4];
                    ldm_x4(bh, baddr);
                    ldm_x4(bl, baddr + (RC_HfL - RC_HfH));
#pragma unroll
                    for (int sel = 0; sel < 2; ++sel) {
                        int nt = nb * 2 + sel;
                        mma_bf16(accC[nt], ah, bh[sel], bh[sel + 2]);
                        mma_bf16(accC[nt], al, bh[sel], bh[sel + 2]);
                        mma_bf16(accC[nt], ah, bl[sel], bl[sel + 2]);
                    }
                }
            }
            // partials -> red[w*16 + row][col], stride 36
#pragma unroll
            for (int nt = 0; nt < 4; ++nt) {
                int col = nt * 8 + tg2;
                *(float2*)&red[(w * 16 + gr) * 36 + col] =
                    make_float2(accC[nt][0], accC[nt][1]);
                *(float2*)&red[(w * 16 + gr + 8) * 36 + col] =
                    make_float2(accC[nt][2], accC[nt][3]);
            }
            __syncthreads();

            // reduce 8 slices + gated scatter
            float accv[2];
#pragma unroll
            for (int j = 0; j < 2; ++j) {
                int cl = tx * 2 + j;
                float s = 0.f;
#pragma unroll
                for (int ks = 0; ks < 8; ++ks)
                    s += red[(ks * 16 + ty) * 36 + cl];
                accv[j] = s;
            }
            float2 outp = *(const float2*)(smc + RC_OuF + ty * 1040 + cc * 4);
            float gx = sigm_(accv[0] + fx.x) * mm.x;
            float gy = sigm_(accv[1] + fx.y) * mm.y;
            if (pm) {
                *(float2*)&g_csh[((size_t)b * NN + pa) * UU + cc] =
                    make_float2(csh_o.x + outp.x, csh_o.y + outp.y);
                *(float2*)&g_gcs[((size_t)b * NN + pa) * UU + cc] =
                    make_float2(gcs_o.x + gx, gcs_o.y + gy);
            }
            if (om) {
                *(float2*)&hs[((size_t)b * NN + tg) * UU + cc] = outp;
            }
        }
        gsync_g(grp);
    }
}

// ---------------------------------------------------------------------------
// Launch: 3 graph nodes.
// ---------------------------------------------------------------------------
extern "C" void kernel_launch(void* const* d_in, const int* in_sizes, int n_in,
                              void* d_out, int out_size)
{
    const float* inputs  = (const float*)d_in[0];
    const int*   parents = (const int*)  d_in[1];
    const int*   post    = (const int*)  d_in[2];
    const float* xf      = (const float*)d_in[3];
    const float* hfk     = (const float*)d_in[4];
    const float* hiou    = (const float*)d_in[5];
    const float* bias    = (const float*)d_in[6];
    float* hs = (float*)d_out;

    (void)in_sizes; (void)n_in; (void)out_size;

    static int smem_set = 0;
    if (!smem_set) {
        cudaFuncSetAttribute(k_recur, cudaFuncAttributeMaxDynamicSharedMemorySize,
                             RC_SMEM);
        cudaFuncSetAttribute(k_precompute_mma,
                             cudaFuncAttributeMaxDynamicSharedMemorySize, PC_SMEM);
        smem_set = 1;
    }

    k_zero<<<2048, 256>>>((float4*)hs);
    k_precompute_mma<<<dim3(8, 512), 256, PC_SMEM>>>(inputs, xf, bias);
    k_recur<<<128, 256, RC_SMEM>>>(parents, post, hfk, hiou, hs);
}

// round 16
// speedup vs baseline: 3.0073x; 1.0083x over previous
#include <cuda_runtime.h>
#include <cuda_bf16.h>
#include <math.h>
#include <stdint.h>

#define BB 256
#define NN 256
#define DD 256
#define UU 256

typedef unsigned long long ull;

// ---------------------------------------------------------------------------
// Scratch (static __device__ arrays; no allocations allowed)
// ---------------------------------------------------------------------------
__device__ float g_fiou[(size_t)BB * NN * 1024];  // [b][n][1024]: 0..255=f, 256..511=i, 512..767=o, 768..1023=u
__device__ float g_csh[(size_t)BB * NN * UU];     // child-sum of hidden
__device__ float g_gcs[(size_t)BB * NN * UU];     // gated child cell sum
__device__ float g_out[BB * UU];                  // out for current step
__device__ float g_mem[BB * UU];                  // mem for current step

// Pre-converted bf16 hi/lo operands for the precompute GEMM
__device__ __nv_bfloat16 g_Xh[(size_t)BB * NN * DD];
__device__ __nv_bfloat16 g_Xl[(size_t)BB * NN * DD];
__device__ __nv_bfloat16 g_Wth[1024 * 256];   // W transposed [n][k], hi
__device__ __nv_bfloat16 g_Wtl[1024 * 256];   // lo

// Per-group barrier state, padded to separate 128B lines.
__device__ unsigned g_cnt[16 * 32];
__device__ volatile unsigned g_genA[16 * 32];

// Fast transcendentals: __expf rel-err ~2^-21, far inside the 1e-3 budget.
__device__ __forceinline__ float sigm_(float x) {
    return __fdividef(1.f, 1.f + __expf(-x));
}
__device__ __forceinline__ float tanh_(float x) {
    x = fminf(fmaxf(x, -15.f), 15.f);
    float e = __expf(2.f * x);
    return __fdividef(e - 1.f, e + 1.f);
}

// Group-local sense-reversal barrier (8 CTAs per group, all co-resident).
__device__ __forceinline__ void gsync_g(int grp) {
    __syncthreads();
    if (threadIdx.x == 0) {
        const int gi = grp * 32;
        unsigned my = g_genA[gi];
        __threadfence();  // release
        if (atomicAdd(&g_cnt[gi], 1u) == 7u) {
            g_cnt[gi] = 0;
            __threadfence();
            g_genA[gi] = my + 1;
        } else {
            while (g_genA[gi] == my) { }
        }
        __threadfence();  // acquire
    }
    __syncthreads();
}

// ---------------------------------------------------------------------------
// Zero csh, gcs, hs (output is poisoned before every timed replay)
// ---------------------------------------------------------------------------
__global__ void k_zero(float4* __restrict__ hs4) {
    const size_t n4 = ((size_t)BB * NN * UU) / 4;
    float4 z = make_float4(0.f, 0.f, 0.f, 0.f);
    float4* c4 = (float4*)g_csh;
    float4* g4 = (float4*)g_gcs;
    for (size_t i = (size_t)blockIdx.x * blockDim.x + threadIdx.x; i < n4;
         i += (size_t)gridDim.x * blockDim.x) {
        c4[i] = z; g4[i] = z; hs4[i] = z;
    }
}

// ---------------------------------------------------------------------------
// mma.sync helpers (layout recipe validated by R13/R14)
// ---------------------------------------------------------------------------
__device__ __forceinline__ uint32_t smem_u32(const void* p) {
    uint32_t a;
    asm("{ .reg .u64 t; cvta.to.shared.u64 t, %1; cvt.u32.u64 %0, t; }"
        : "=r"(a) : "l"(p));
    return a;
}
// pack two fp32 -> bf16x2 (x -> low half, y -> high half)
__device__ __forceinline__ uint32_t bf2(float x, float y) {
    uint32_t r;
    asm("cvt.rn.bf16x2.f32 %0, %1, %2;" : "=r"(r) : "f"(y), "f"(x));
    return r;
}
__device__ __forceinline__ void ldm_x4(uint32_t (&r)[4], uint32_t addr) {
    asm volatile("ldmatrix.sync.aligned.m8n8.x4.shared.b16 {%0,%1,%2,%3}, [%4];"
        : "=r"(r[0]), "=r"(r[1]), "=r"(r[2]), "=r"(r[3]) : "r"(addr));
}
__device__ __forceinline__ void mma_bf16(float (&d)[4], const uint32_t (&a)[4],
                                         uint32_t b0, uint32_t b1) {
    asm volatile(
        "mma.sync.aligned.m16n8k16.row.col.f32.bf16.bf16.f32 "
        "{%0,%1,%2,%3}, {%4,%5,%6,%7}, {%8,%9}, {%0,%1,%2,%3};"
        : "+f"(d[0]), "+f"(d[1]), "+f"(d[2]), "+f"(d[3])
        : "r"(a[0]), "r"(a[1]), "r"(a[2]), "r"(a[3]), "r"(b0), "r"(b1));
}

// ---------------------------------------------------------------------------
// One-time operand conversion: X -> bf16 hi/lo; W -> transposed bf16 hi/lo
// ---------------------------------------------------------------------------
__global__ void k_convX(const float4* __restrict__ X4) {
    size_t i = (size_t)blockIdx.x * blockDim.x + threadIdx.x;  // 4,194,304
    float4 v = X4[i];
    float hx = __bfloat162float(__float2bfloat16(v.x));
    float hy = __bfloat162float(__float2bfloat16(v.y));
    float hz = __bfloat162float(__float2bfloat16(v.z));
    float hw = __bfloat162float(__float2bfloat16(v.w));
    ((uint2*)g_Xh)[i] = make_uint2(bf2(v.x, v.y), bf2(v.z, v.w));
    ((uint2*)g_Xl)[i] = make_uint2(bf2(v.x - hx, v.y - hy), bf2(v.z - hz, v.w - hw));
}

__global__ void k_convW(const float* __restrict__ W) {
    int i = blockIdx.x * 256 + threadIdx.x;   // 65536 threads; i = n*64 + q
    int n = i >> 6, q = i & 63;
    float w0 = W[(size_t)(q * 4 + 0) * 1024 + n];
    float w1 = W[(size_t)(q * 4 + 1) * 1024 + n];
    float w2 = W[(size_t)(q * 4 + 2) * 1024 + n];
    float w3 = W[(size_t)(q * 4 + 3) * 1024 + n];
    float h0 = __bfloat162float(__float2bfloat16(w0));
    float h1 = __bfloat162float(__float2bfloat16(w1));
    float h2 = __bfloat162float(__float2bfloat16(w2));
    float h3 = __bfloat162float(__float2bfloat16(w3));
    ((uint2*)g_Wth)[i] = make_uint2(bf2(w0, w1), bf2(w2, w3));
    ((uint2*)g_Wtl)[i] = make_uint2(bf2(w0 - h0, w1 - h1), bf2(w2 - h2, w3 - h3));
}

// ===========================================================================
// Tensor-core precompute; staging is now pure copy of pre-converted bf16.
// Smem image identical to R13/R14 (mma loop untouched).
// ===========================================================================
#define PC_AH 0
#define PC_AL 20480
#define PC_BH 40960
#define PC_BL 61440
#define PC_SMEM 81920

__global__ void __launch_bounds__(256, 1) k_precompute_mma(
    const float* __restrict__ bias)
{
    extern __shared__ __align__(16) char smc[];
    const uint32_t sb = smem_u32(smc);
    const int tid  = threadIdx.x;
    const int lane = tid & 31;
    const int w    = tid >> 5;
    const int wm   = w >> 2;
    const int wn   = w & 3;
    const int N0   = blockIdx.x * 128;
    const int M0   = blockIdx.y * 128;

    float acc[4][4][4];
#pragma unroll
    for (int mi = 0; mi < 4; ++mi)
#pragma unroll
        for (int ni = 0; ni < 4; ++ni)
#pragma unroll
            for (int q = 0; q < 4; ++q) acc[mi][ni][q] = 0.f;

    for (int kc = 0; kc < 256; kc += 64) {
        if (kc) __syncthreads();

        // A tile: 128 rows x 64 k, hi+lo (pure 16B copies)
#pragma unroll
        for (int it = 0; it < 4; ++it) {
            int i = tid + it * 256;
            int r = i >> 3, q = i & 7;
            size_t src = (size_t)(M0 + r) * DD + kc + q * 8;
            uint32_t off = (uint32_t)(r * 160 + q * 16);
            *(uint4*)(smc + PC_AH + off) = *(const uint4*)&g_Xh[src];
            *(uint4*)(smc + PC_AL + off) = *(const uint4*)&g_Xl[src];
        }
        // B tile: 128 cols x 64 k from pre-transposed Wt
#pragma unroll
        for (int it = 0; it < 4; ++it) {
            int i = tid + it * 256;
            int n = i >> 3, q = i & 7;
            size_t src = (size_t)(N0 + n) * 256 + kc + q * 8;
            uint32_t off = (uint32_t)(n * 160 + q * 16);
            *(uint4*)(smc + PC_BH + off) = *(const uint4*)&g_Wth[src];
            *(uint4*)(smc + PC_BL + off) = *(const uint4*)&g_Wtl[src];
        }
        __syncthreads();

#pragma unroll
        for (int kk = 0; kk < 4; ++kk) {
            const uint32_t kb = (uint32_t)(kk * 32 + (lane >> 4) * 16);
            uint32_t ah[4][4], al[4][4];
#pragma unroll
            for (int mi = 0; mi < 4; ++mi) {
                uint32_t ro = (uint32_t)((wm * 64 + mi * 16 + (lane & 15)) * 160) + kb;
                ldm_x4(ah[mi], sb + PC_AH + ro);
                ldm_x4(al[mi], sb + PC_AL + ro);
            }
            uint32_t bh[2][4], bl[2][4];
#pragma unroll
            for (int nj = 0; nj < 2; ++nj) {
                uint32_t ro = (uint32_t)((wn * 32 + nj * 16 + (lane & 15)) * 160) + kb;
                ldm_x4(bh[nj], sb + PC_BH + ro);
                ldm_x4(bl[nj], sb + PC_BL + ro);
            }
#pragma unroll
            for (int mi = 0; mi < 4; ++mi)
#pragma unroll
                for (int ni = 0; ni < 4; ++ni) {
                    int nj = ni >> 1, sel = ni & 1;
                    uint32_t bh0 = bh[nj][sel], bh1 = bh[nj][sel + 2];
                    mma_bf16(acc[mi][ni], ah[mi], bh0, bh1);
                    mma_bf16(acc[mi][ni], al[mi], bh0, bh1);
                    mma_bf16(acc[mi][ni], ah[mi], bl[nj][sel], bl[nj][sel + 2]);
                }
        }
    }

    const int gr = lane >> 2, tg = lane & 3;
#pragma unroll
    for (int ni = 0; ni < 4; ++ni) {
        int col = N0 + wn * 32 + ni * 8 + tg * 2;
        float2 bv = *(const float2*)&bias[col];
#pragma unroll
        for (int mi = 0; mi < 4; ++mi) {
            int row = M0 + wm * 64 + mi * 16 + gr;
            *(float2*)&g_fiou[(size_t)row * 1024 + col] =
                make_float2(acc[mi][ni][0] + bv.x, acc[mi][ni][1] + bv.y);
            *(float2*)&g_fiou[(size_t)(row + 8) * 1024 + col] =
                make_float2(acc[mi][ni][2] + bv.x, acc[mi][ni][3] + bv.y);
        }
    }
}

// ===========================================================================
// Persistent recurrence (byte-identical to R14, passing)
// ===========================================================================
#define RC_WtH 0
#define RC_WtL 50688
#define RC_HfH 101376
#define RC_HfL 118272
#define RC_AsH 135168
#define RC_AsL 143616
#define RC_OuH 152064
#define RC_OuL 160512
#define RC_OuF 168960
#define RC_RED 185600
#define RC_SMEM 211200

__global__ void __launch_bounds__(256, 1) k_recur(
    const int*   __restrict__ parents,
    const int*   __restrict__ post,
    const float* __restrict__ hf,
    const float* __restrict__ hiou,
    float*       __restrict__ hs)
{
    extern __shared__ __align__(16) char smc[];
    const uint32_t sb = smem_u32(smc);
    float* red = (float*)(smc + RC_RED);

    const int c    = blockIdx.x;
    const int grp  = c >> 3;
    const int cig  = c & 7;
    const int tid  = threadIdx.x;
    const int lane = tid & 31;
    const int w    = tid >> 5;
    const int tx   = tid & 15;
    const int ty   = tid >> 4;

    const int bG0 = grp * 16;
    const int uA0 = cig * 32;
    const int cC0 = cig * 32;

    // ---- one-time weight staging: transposed, bf16 hi/lo ----
    for (int e = tid; e < 24576; e += 256) {
        int col = e % 96, k = e / 96;
        int gate = col >> 5, unit = col & 31;
        float v = hiou[(size_t)k * 768 + gate * 256 + uA0 + unit];
        __nv_bfloat16 h = __float2bfloat16(v);
        *(__nv_bfloat16*)(smc + RC_WtH + col * 528 + k * 2) = h;
        *(__nv_bfloat16*)(smc + RC_WtL + col * 528 + k * 2) =
            __float2bfloat16(v - __bfloat162float(h));
    }
    for (int e = tid; e < 8192; e += 256) {
        int col = e & 31, k = e >> 5;
        float v = hf[(size_t)k * 256 + cC0 + col];
        __nv_bfloat16 h = __float2bfloat16(v);
        *(__nv_bfloat16*)(smc + RC_HfH + col * 528 + k * 2) = h;
        *(__nv_bfloat16*)(smc + RC_HfL + col * 528 + k * 2) =
            __float2bfloat16(v - __bfloat162float(h));
    }
    __syncthreads();

    const int gr  = lane >> 2;
    const int tg2 = (lane & 3) * 2;

    for (int t = 0; t < NN; ++t) {
        // ================= Phase A: GEMM1 (mma) + gates =================
        {
            const int bA = bG0 + ty;
            const int u2 = uA0 + tx * 2;
            int poA = post[bA * NN + t];
            int tgA = poA < 0 ? 0 : poA;
            size_t fb = ((size_t)bA * NN + tgA) * 1024 + u2;
            float2 fi = *(const float2*)&g_fiou[fb + 256];
            float2 fo = *(const float2*)&g_fiou[fb + 512];
            float2 fu = *(const float2*)&g_fiou[fb + 768];
            float2 gc = __ldcg((const float2*)&g_gcs[((size_t)bA * NN + tgA) * UU + u2]);

            {
                int r = tid >> 4, q0 = tid & 15;
                int po = post[(bG0 + r) * NN + t];
                int tg = po < 0 ? 0 : po;
                const float4* src =
                    (const float4*)&g_csh[(((size_t)(bG0 + r)) * NN + tg) * UU];
#pragma unroll
                for (int j = 0; j < 4; ++j) {
                    float4 v = __ldcg(&src[q0 + j * 16]);
                    float hx = __bfloat162float(__float2bfloat16(v.x));
                    float hy = __bfloat162float(__float2bfloat16(v.y));
                    float hz = __bfloat162float(__float2bfloat16(v.z));
                    float hw = __bfloat162float(__float2bfloat16(v.w));
                    uint32_t off = (uint32_t)(r * 528 + (q0 + j * 16) * 8);
                    *(uint2*)(smc + RC_AsH + off) =
                        make_uint2(bf2(v.x, v.y), bf2(v.z, v.w));
                    *(uint2*)(smc + RC_AsL + off) =
                        make_uint2(bf2(v.x - hx, v.y - hy), bf2(v.z - hz, v.w - hw));
                }
            }
            __syncthreads();

            const int ks = w & 3;
            const int ch = w >> 2;
            float acc[6][4];
#pragma unroll
            for (int nt = 0; nt < 6; ++nt)
#pragma unroll
                for (int q = 0; q < 4; ++q) acc[nt][q] = 0.f;

#pragma unroll
            for (int kk = 0; kk < 4; ++kk) {
                const uint32_t kb = (uint32_t)((ks * 64 + kk * 16) * 2 + (lane >> 4) * 16);
                uint32_t ah[4], al[4];
                uint32_t aaddr = sb + RC_AsH + (uint32_t)((lane & 15) * 528) + kb;
                ldm_x4(ah, aaddr);
                ldm_x4(al, aaddr + (RC_AsL - RC_AsH));
#pragma unroll
                for (int nb = 0; nb < 3; ++nb) {
                    uint32_t baddr = sb + RC_WtH +
                        (uint32_t)((ch * 48 + nb * 16 + (lane & 15)) * 528) + kb;
                    uint32_t bh[4], bl[4];
                    ldm_x4(bh, baddr);
                    ldm_x4(bl, baddr + (RC_WtL - RC_WtH));
#pragma unroll
                    for (int sel = 0; sel < 2; ++sel) {
                        int nt = nb * 2 + sel;
                        mma_bf16(acc[nt], ah, bh[sel], bh[sel + 2]);
                        mma_bf16(acc[nt], al, bh[sel], bh[sel + 2]);
                        mma_bf16(acc[nt], ah, bl[sel], bl[sel + 2]);
                    }
                }
            }
#pragma unroll
            for (int nt = 0; nt < 6; ++nt) {
                int col = ch * 48 + nt * 8 + tg2;
                *(float2*)&red[(ks * 16 + gr) * 100 + col] =
                    make_float2(acc[nt][0], acc[nt][1]);
                *(float2*)&red[(ks * 16 + gr + 8) * 100 + col] =
                    make_float2(acc[nt][2], acc[nt][3]);
            }
            __syncthreads();

            float memv[2], outv[2];
#pragma unroll
            for (int j = 0; j < 2; ++j) {
                int u = tx * 2 + j;
                float aI = 0.f, aO = 0.f, aU = 0.f;
#pragma unroll
                for (int s = 0; s < 4; ++s) {
                    int rb = (s * 16 + ty) * 100;
                    aI += red[rb + u];
                    aO += red[rb + 32 + u];
                    aU += red[rb + 64 + u];
                }
                float fiv = j ? fi.y : fi.x;
                float fov = j ? fo.y : fo.x;
                float fuv = j ? fu.y : fu.x;
                float gcv = j ? gc.y : gc.x;
                memv[j] = sigm_(aI + fiv) * tanh_(aU + fuv) + gcv;
                outv[j] = sigm_(aO + fov) * tanh_(memv[j]);
            }
            *(float2*)&g_out[bA * UU + u2] = make_float2(outv[0], outv[1]);
            *(float2*)&g_mem[bA * UU + u2] = make_float2(memv[0], memv[1]);
        }
        gsync_g(grp);

        // ================= Phase C: GEMM2 (mma) + gated scatter =================
        {
            const int b  = bG0 + ty;
            const int cc = cC0 + tx * 2;
            int po = post[b * NN + t];
            int om = po >= 0;
            int tg = om ? po : 0;
            int pr = parents[b * NN + tg];
            int pm = om && (pr >= 0);
            int pa = pr < 0 ? 0 : pr;
            float2 fx    = *(const float2*)&g_fiou[((size_t)b * NN + pa) * 1024 + cc];
            float2 csh_o = *(const float2*)&g_csh[((size_t)b * NN + pa) * UU + cc];
            float2 gcs_o = *(const float2*)&g_gcs[((size_t)b * NN + pa) * UU + cc];
            float2 mm    = __ldcg((const float2*)&g_mem[b * UU + cc]);

            {
                int r = tid >> 4, q0 = tid & 15;
                const float4* src = (const float4*)&g_out[(bG0 + r) * UU];
#pragma unroll
                for (int j = 0; j < 4; ++j) {
                    float4 v = __ldcg(&src[q0 + j * 16]);
                    int q = q0 + j * 16;
                    *(float4*)(smc + RC_OuF + r * 1040 + q * 16) = v;
                    float hx = __bfloat162float(__float2bfloat16(v.x));
                    float hy = __bfloat162float(__float2bfloat16(v.y));
                    float hz = __bfloat162float(__float2bfloat16(v.z));
                    float hw = __bfloat162float(__float2bfloat16(v.w));
                    uint32_t off = (uint32_t)(r * 528 + q * 8);
                    *(uint2*)(smc + RC_OuH + off) =
                        make_uint2(bf2(v.x, v.y), bf2(v.z, v.w));
                    *(uint2*)(smc + RC_OuL + off) =
                        make_uint2(bf2(v.x - hx, v.y - hy), bf2(v.z - hz, v.w - hw));
                }
            }
            __syncthreads();

            float accC[4][4];
#pragma unroll
            for (int nt = 0; nt < 4; ++nt)
#pragma unroll
                for (int q = 0; q < 4; ++q) accC[nt][q] = 0.f;

#pragma unroll
            for (int kk = 0; kk < 2; ++kk) {
                const uint32_t kb = (uint32_t)((w * 32 + kk * 16) * 2 + (lane >> 4) * 16);
                uint32_t ah[4], al[4];
                uint32_t aaddr = sb + RC_OuH + (uint32_t)((lane & 15) * 528) + kb;
                ldm_x4(ah, aaddr);
                ldm_x4(al, aaddr + (RC_OuL - RC_OuH));
#pragma unroll
                for (int nb = 0; nb < 2; ++nb) {
                    uint32_t baddr = sb + RC_HfH +
                        (uint32_t)((nb * 16 + (lane & 15)) * 528) + kb;
                    uint32_t bh[4], bl[4];
                    ldm_x4(bh, baddr);
                    ldm_x4(bl, baddr + (RC_HfL - RC_HfH));
#pragma unroll
                    for (int sel = 0; sel < 2; ++sel) {
                        int nt = nb * 2 + sel;
                        mma_bf16(accC[nt], ah, bh[sel], bh[sel + 2]);
                        mma_bf16(accC[nt], al, bh[sel], bh[sel + 2]);
                        mma_bf16(accC[nt], ah, bl[sel], bl[sel + 2]);
                    }
                }
            }
#pragma unroll
            for (int nt = 0; nt < 4; ++nt) {
                int col = nt * 8 + tg2;
                *(float2*)&red[(w * 16 + gr) * 36 + col] =
                    make_float2(accC[nt][0], accC[nt][1]);
                *(float2*)&red[(w * 16 + gr + 8) * 36 + col] =
                    make_float2(accC[nt][2], accC[nt][3]);
            }
            __syncthreads();

            float accv[2];
#pragma unroll
            for (int j = 0; j < 2; ++j) {
                int cl = tx * 2 + j;
                float s = 0.f;
#pragma unroll
                for (int ks = 0; ks < 8; ++ks)
                    s += red[(ks * 16 + ty) * 36 + cl];
                accv[j] = s;
            }
            float2 outp = *(const float2*)(smc + RC_OuF + ty * 1040 + cc * 4);
            float gx = sigm_(accv[0] + fx.x) * mm.x;
            float gy = sigm_(accv[1] + fx.y) * mm.y;
            if (pm) {
                *(float2*)&g_csh[((size_t)b * NN + pa) * UU + cc] =
                    make_float2(csh_o.x + outp.x, csh_o.y + outp.y);
                *(float2*)&g_gcs[((size_t)b * NN + pa) * UU + cc] =
                    make_float2(gcs_o.x + gx, gcs_o.y + gy);
            }
            if (om) {
                *(float2*)&hs[((size_t)b * NN + tg) * UU + cc] = outp;
            }
        }
        gsync_g(grp);
    }
}

// ---------------------------------------------------------------------------
// Launch: 5 graph nodes.
// ---------------------------------------------------------------------------
extern "C" void kernel_launch(void* const* d_in, const int* in_sizes, int n_in,
                              void* d_out, int out_size)
{
    const float* inputs  = (const float*)d_in[0];
    const int*   parents = (const int*)  d_in[1];
    const int*   post    = (const int*)  d_in[2];
    const float* xf      = (const float*)d_in[3];
    const float* hfk     = (const float*)d_in[4];
    const float* hiou    = (const float*)d_in[5];
    const float* bias    = (const float*)d_in[6];
    float* hs = (float*)d_out;

    (void)in_sizes; (void)n_in; (void)out_size;

    static int smem_set = 0;
    if (!smem_set) {
        cudaFuncSetAttribute(k_recur, cudaFuncAttributeMaxDynamicSharedMemorySize,
                             RC_SMEM);
        cudaFuncSetAttribute(k_precompute_mma,
                             cudaFuncAttributeMaxDynamicSharedMemorySize, PC_SMEM);
        smem_set = 1;
    }

    k_zero<<<2048, 256>>>((float4*)hs);
    k_convX<<<16384, 256>>>((const float4*)inputs);
    k_convW<<<256, 256>>>(xf);
    k_precompute_mma<<<dim3(8, 512), 256, PC_SMEM>>>(bias);
    k_recur<<<128, 256, RC_SMEM>>>(parents, post, hfk, hiou, hs);
}